// round 7
// baseline (speedup 1.0000x reference)
#include <cuda_runtime.h>
#include <cstdint>

// Problem constants
#define NB 32      // batch
#define TT 512     // time steps
#define DD 512     // input dim
#define HH 1024    // hidden dim
#define GG 3072    // 3*H

#define NCTA 128   // persistent grid
#define NTHR 256

#define WPAD 1028  // padded weight column stride (floats)
#define WPAD4 257  // in float4 units

// Scratch (module-load allocated; no runtime alloc)
__device__ float g_gates[(size_t)NB * TT * GG];  // 16384 x 3072
__device__ float g_zr[NB * 2 * HH];              // 32 x 2048
__device__ unsigned g_rmask[TT];                 // per-step reset bitmasks

// Hierarchical barrier state (zeroed by epilogue BEFORE gru each replay)
__device__ unsigned g_leaf[16];
__device__ unsigned g_root;
__device__ unsigned g_release;

// packed f32x2 fma: acc = a*b + acc (each u64 = 2 packed floats)
#define FMA2(acc, a, b) \
    asm("fma.rn.f32x2 %0, %1, %2, %0;" : "+l"(acc) : "l"(a), "l"(b))

__device__ __forceinline__ unsigned long long dup2(float v)
{
    unsigned long long r;
    asm("mov.b64 %0, {%1, %1};" : "=l"(r) : "f"(v));
    return r;
}

__device__ __forceinline__ float sum2(unsigned long long v)
{
    float2 p = *reinterpret_cast<float2*>(&v);
    return p.x + p.y;
}

// ---------------------------------------------------------------------------
// Prep: detect reset dtype (bool8 vs int32), build per-step bitmasks.
// ---------------------------------------------------------------------------
__global__ void prep_reset(const unsigned char* __restrict__ raw)
{
    __shared__ int s_bool8;
    int tid = threadIdx.x;
    if (tid == 0) s_bool8 = 0;
    __syncthreads();
    for (int i = tid; i < 4096; i += blockDim.x)
        if ((i & 3) != 0 && raw[i] != 0) s_bool8 = 1;
    __syncthreads();
    bool b8 = (s_bool8 != 0);
    const int* r32 = (const int*)raw;
    for (int t = tid; t < TT; t += blockDim.x) {
        unsigned m = 0;
        for (int b = 0; b < NB; b++) {
            bool rv = b8 ? (raw[b * TT + t] != 0) : (r32[b * TT + t] != 0);
            if (rv) m |= (1u << b);
        }
        if (t == 0) m = 0xFFFFFFFFu;
        g_rmask[t] = m;
    }
}

// ---------------------------------------------------------------------------
// GEMM: gates = X(16384x512) @ Wi(512x3072) + bias   (f32x2 micro-kernel)
// ---------------------------------------------------------------------------
__global__ __launch_bounds__(256) void gemm_gates(
    const float* __restrict__ X, const float* __restrict__ Wi,
    const float* __restrict__ bias)
{
    const int K = DD;
    const int Nn = GG;

    __shared__ float As[8][128];
    __shared__ float Bs[8][128];

    const int bm = blockIdx.y * 128;
    const int bn = blockIdx.x * 128;
    const int tid = threadIdx.x;

    const int aRow = tid >> 1;
    const int aCol = (tid & 1) << 2;
    const int bRow = tid >> 5;
    const int bCol = (tid & 31) << 2;

    const int tRow = (tid >> 4) << 3;
    const int tCol = (tid & 15) << 3;

    unsigned long long acc2[8][4];
#pragma unroll
    for (int i = 0; i < 8; i++)
#pragma unroll
        for (int j = 0; j < 4; j++) acc2[i][j] = 0ull;

    for (int k0 = 0; k0 < K; k0 += 8) {
        float4 a4 = *reinterpret_cast<const float4*>(
            X + (size_t)(bm + aRow) * K + k0 + aCol);
        As[aCol + 0][aRow] = a4.x;
        As[aCol + 1][aRow] = a4.y;
        As[aCol + 2][aRow] = a4.z;
        As[aCol + 3][aRow] = a4.w;
        *reinterpret_cast<float4*>(&Bs[bRow][bCol]) =
            *reinterpret_cast<const float4*>(Wi + (size_t)(k0 + bRow) * Nn + bn + bCol);
        __syncthreads();

#pragma unroll
        for (int kk = 0; kk < 8; kk++) {
            float4 a0 = *reinterpret_cast<const float4*>(&As[kk][tRow]);
            float4 a1 = *reinterpret_cast<const float4*>(&As[kk][tRow + 4]);
            ulonglong2 b01 = *reinterpret_cast<const ulonglong2*>(&Bs[kk][tCol]);
            ulonglong2 b23 = *reinterpret_cast<const ulonglong2*>(&Bs[kk][tCol + 4]);
            float ar[8] = {a0.x, a0.y, a0.z, a0.w, a1.x, a1.y, a1.z, a1.w};
#pragma unroll
            for (int i = 0; i < 8; i++) {
                unsigned long long aa = dup2(ar[i]);
                FMA2(acc2[i][0], aa, b01.x);
                FMA2(acc2[i][1], aa, b01.y);
                FMA2(acc2[i][2], aa, b23.x);
                FMA2(acc2[i][3], aa, b23.y);
            }
        }
        __syncthreads();
    }

#pragma unroll
    for (int i = 0; i < 8; i++) {
#pragma unroll
        for (int j2 = 0; j2 < 4; j2 += 2) {
            unsigned long long v0 = acc2[i][j2];
            unsigned long long v1 = acc2[i][j2 + 1];
            float2 p0 = *reinterpret_cast<float2*>(&v0);
            float2 p1 = *reinterpret_cast<float2*>(&v1);
            int j = j2 * 2;
            float4 v;
            v.x = p0.x + bias[bn + tCol + j + 0];
            v.y = p0.y + bias[bn + tCol + j + 1];
            v.z = p1.x + bias[bn + tCol + j + 2];
            v.w = p1.y + bias[bn + tCol + j + 3];
            *reinterpret_cast<float4*>(
                g_gates + (size_t)(bm + tRow + i) * Nn + bn + tCol + j) = v;
        }
    }
}

extern __shared__ float dsm[];

// ---------------------------------------------------------------------------
// Persistent recurrence kernel (v4: batch+col register blocking)
// CTA x owns zr cols [16x,16x+16) and a cols [8x,8x+8), all 32 batches.
// smem: w_s 24 x 1028 floats (98688B) + hp4 8192 float4 (131072B) +
//       red 672 floats (2688B) = 232448 B
// ---------------------------------------------------------------------------
__global__ __launch_bounds__(NTHR, 1) void gru_persistent(
    const float* __restrict__ w_h, const float* __restrict__ h0,
    float* out0, float* __restrict__ out1)
{
    float* w_s = dsm;                                  // 24*WPAD floats
    float4* hp4 = (float4*)(dsm + 24 * WPAD);          // 8192 float4
    float* red = dsm + 24 * WPAD + 32768;              // 672 floats
    float* aout = red + 320;                           // phase2 a-values (256)

    const int x = blockIdx.x;
    const int tid = threadIdx.x;
    const int lane = tid & 31;
    const int wp = tid >> 5;
    const int leaf = x & 15;

    const int c_l = lane >> 3;     // 0..3 column lane
    const int b_l = lane & 7;      // 0..7 batch lane

    // phase1 warp coords: (kh, cg, bh)
    const int p1_kh = wp >> 2;
    const int p1_cg = (wp >> 1) & 1;
    const int p1_bh = wp & 1;
    const int p1_b0 = p1_bh * 16 + b_l;        // + 8r for r=0,1
    const int p1_c0 = p1_cg * 8 + c_l;         // + 4s for s=0,1
    const int p1_k0 = p1_kh * 128;

    // phase2 warp coords: (kh, bh, ch)
    const int p2_ch = wp & 1;
    const int p2_bh = (wp >> 1) & 1;
    const int p2_kh = wp >> 2;
    const int p2_b0 = p2_bh * 16 + b_l;
    const int p2_c  = p2_ch * 4 + c_l;         // local a col 0..7
    const int p2_k0 = p2_kh * 128;

    // ---- one-time weight preload: w_s[c*WPAD + k] ----
    for (int i = tid; i < 24 * 1024; i += NTHR) {
        int c = i % 24;
        int k = i / 24;
        int gcol = (c < 16) ? (x * 16 + c) : (2048 + x * 8 + (c - 16));
        w_s[c * WPAD + k] = w_h[(size_t)k * GG + gcol];
    }
    __syncthreads();

    const float4* h0_4 = (const float4*)h0;
    const float4* out0_4 = (const float4*)out0;
    const float4* gzr4 = (const float4*)g_zr;
    const ulonglong2* hu2 = (const ulonglong2*)hp4;
    const ulonglong2* wu2 = (const ulonglong2*)w_s;
    const float4* aout4 = (const float4*)aout;

    // finalize-thread coords (tid < 64)
    const int f_b = tid >> 1;
    const int f_q = tid & 1;

    for (int t = 0; t < TT; t++) {
        // ---- independent prefetches (overlap with barrier-2 wait) ----
        float gx1[4];
        if (p1_kh == 0) {
            const float* gr0 = g_gates + ((size_t)p1_b0 * TT + t) * GG + x * 16;
            const float* gr1 = g_gates + ((size_t)(p1_b0 + 8) * TT + t) * GG + x * 16;
            gx1[0] = gr0[p1_c0];
            gx1[1] = gr0[p1_c0 + 4];
            gx1[2] = gr1[p1_c0];
            gx1[3] = gr1[p1_c0 + 4];
        }
        unsigned rm = g_rmask[t];
        int tp = (t > 0) ? (t - 1) : 0;

        // ---- wait for barrier 2 of previous step (h(t-1) ready) ----
        if (t > 0) {
            unsigned n = 2u * t;
            if (tid == 0) {
                while (*(volatile unsigned*)&g_release < n) __nanosleep(32);
                __threadfence();
            }
            __syncthreads();
        }

        // ---- stage h_eff (all 32 batches) into hp4, swizzled ----
#pragma unroll 4
        for (int b = 0; b < 32; b++) {
            float4 v;
            if ((rm >> b) & 1u)
                v = h0_4[tid];
            else
                v = __ldcg(&out0_4[((size_t)b * TT + tp) * 256 + tid]);
            hp4[b * 256 + (tid ^ (b & 7))] = v;
        }
        __syncthreads();

        // ---- phase1 FMA: 2b x 2c register tile, half-k per warp ----
        {
            unsigned long long a00 = 0, a01 = 0, a10 = 0, a11 = 0;
            const ulonglong2* hA = hu2 + p1_b0 * 256;
            const ulonglong2* hB = hu2 + (p1_b0 + 8) * 256;
            const ulonglong2* wA = wu2 + p1_c0 * WPAD4;
            const ulonglong2* wB = wA + 4 * WPAD4;
#pragma unroll 4
            for (int k4 = p1_k0; k4 < p1_k0 + 128; ++k4) {
                int hk = k4 ^ b_l;
                ulonglong2 hv0 = hA[hk];
                ulonglong2 hv1 = hB[hk];
                ulonglong2 wv0 = wA[k4];
                ulonglong2 wv1 = wB[k4];
                FMA2(a00, hv0.x, wv0.x); FMA2(a00, hv0.y, wv0.y);
                FMA2(a01, hv0.x, wv1.x); FMA2(a01, hv0.y, wv1.y);
                FMA2(a10, hv1.x, wv0.x); FMA2(a10, hv1.y, wv0.y);
                FMA2(a11, hv1.x, wv1.x); FMA2(a11, hv1.y, wv1.y);
            }
            if (p1_kh == 1) {
                red[(p1_c0)     * 40 + p1_b0]     = sum2(a00);
                red[(p1_c0 + 4) * 40 + p1_b0]     = sum2(a01);
                red[(p1_c0)     * 40 + p1_b0 + 8] = sum2(a10);
                red[(p1_c0 + 4) * 40 + p1_b0 + 8] = sum2(a11);
            }
            __syncthreads();
            if (p1_kh == 0) {
                float s0 = sum2(a00) + red[(p1_c0)     * 40 + p1_b0];
                float s1 = sum2(a01) + red[(p1_c0 + 4) * 40 + p1_b0];
                float s2 = sum2(a10) + red[(p1_c0)     * 40 + p1_b0 + 8];
                float s3 = sum2(a11) + red[(p1_c0 + 4) * 40 + p1_b0 + 8];
                float* z0 = g_zr + p1_b0 * 2048 + x * 16;
                float* z1 = g_zr + (p1_b0 + 8) * 2048 + x * 16;
                z0[p1_c0]     = 1.0f / (1.0f + __expf(-(gx1[0] + s0)));
                z0[p1_c0 + 4] = 1.0f / (1.0f + __expf(-(gx1[1] + s1)));
                z1[p1_c0]     = 1.0f / (1.0f + __expf(-(gx1[2] + s2)));
                z1[p1_c0 + 4] = 1.0f / (1.0f + __expf(-(gx1[3] + s3)));
            }
        }

        // ---- barrier 1 arrive (zr ready) ----
        unsigned n1 = 2u * t + 1u;
        __syncthreads();
        if (tid == 0) {
            __threadfence();
            unsigned o = atomicAdd(&g_leaf[leaf], 1u);
            if (o == n1 * 8u - 1u) {
                unsigned o2 = atomicAdd(&g_root, 1u);
                if (o2 == n1 * 16u - 1u) atomicExch(&g_release, n1);
            }
        }

        // ---- overlap: prefetch local data while waiting ----
        float gx2a = 0.f, gx2b = 0.f;
        if (p2_kh == 0) {
            const float* ga = g_gates + ((size_t)p2_b0 * TT + t) * GG + 2048 + x * 8;
            const float* gb = g_gates + ((size_t)(p2_b0 + 8) * TT + t) * GG + 2048 + x * 8;
            gx2a = ga[p2_c];
            gx2b = gb[p2_c];
        }
        float4 hown;
        if (tid < 64)
            hown = hp4[f_b * 256 + ((x * 2 + f_q) ^ (f_b & 7))];

        // ---- barrier 1 wait ----
        if (tid == 0) {
            while (*(volatile unsigned*)&g_release < n1) __nanosleep(32);
            __threadfence();
        }
        __syncthreads();

        float4 z4;
        if (tid < 64)
            z4 = __ldcg(&gzr4[f_b * 512 + x * 2 + f_q]);

        // ---- stage rh = r * h in place ----
#pragma unroll 4
        for (int b = 0; b < 32; b++) {
            int sidx = b * 256 + (tid ^ (b & 7));
            float4 h = hp4[sidx];
            float4 r = __ldcg(&gzr4[b * 512 + 256 + tid]);
            h.x *= r.x; h.y *= r.y; h.z *= r.z; h.w *= r.w;
            hp4[sidx] = h;
        }
        __syncthreads();

        // ---- phase2 FMA: 2b x 1c register tile, half-k per warp ----
        {
            unsigned long long a0 = 0, a1 = 0;
            const ulonglong2* hA = hu2 + p2_b0 * 256;
            const ulonglong2* hB = hu2 + (p2_b0 + 8) * 256;
            const ulonglong2* wA = wu2 + (16 + p2_c) * WPAD4;
#pragma unroll 4
            for (int k4 = p2_k0; k4 < p2_k0 + 128; ++k4) {
                int hk = k4 ^ b_l;
                ulonglong2 hv0 = hA[hk];
                ulonglong2 hv1 = hB[hk];
                ulonglong2 wv = wA[k4];
                FMA2(a0, hv0.x, wv.x); FMA2(a0, hv0.y, wv.y);
                FMA2(a1, hv1.x, wv.x); FMA2(a1, hv1.y, wv.y);
            }
            if (p2_kh == 1) {
                red[p2_c * 40 + p2_b0]     = sum2(a0);
                red[p2_c * 40 + p2_b0 + 8] = sum2(a1);
            }
            __syncthreads();
            if (p2_kh == 0) {
                float s0 = sum2(a0) + red[p2_c * 40 + p2_b0];
                float s1 = sum2(a1) + red[p2_c * 40 + p2_b0 + 8];
                aout[p2_b0 * 8 + p2_c]       = tanhf(gx2a + s0);
                aout[(p2_b0 + 8) * 8 + p2_c] = tanhf(gx2b + s1);
            }
            __syncthreads();
        }

        // ---- finalize: h_next = (1-z)h + z*a, write both outputs ----
        if (tid < 64) {
            float4 av = aout4[tid];
            float4 hn;
            hn.x = (1.0f - z4.x) * hown.x + z4.x * av.x;
            hn.y = (1.0f - z4.y) * hown.y + z4.y * av.y;
            hn.z = (1.0f - z4.z) * hown.z + z4.z * av.z;
            hn.w = (1.0f - z4.w) * hown.w + z4.w * av.w;
            size_t o4 = ((size_t)f_b * TT + t) * 256 + x * 2 + f_q;
            ((float4*)out0)[o4] = hn;
            ((float4*)out1)[o4] = hn;
        }

        // ---- barrier 2 arrive (h(t) ready); wait at next loop top ----
        unsigned n2 = 2u * t + 2u;
        __syncthreads();
        if (tid == 0) {
            __threadfence();
            unsigned o = atomicAdd(&g_leaf[leaf], 1u);
            if (o == n2 * 8u - 1u) {
                unsigned o2 = atomicAdd(&g_root, 1u);
                if (o2 == n2 * 16u - 1u) atomicExch(&g_release, n2);
            }
        }
    }
}

// ---------------------------------------------------------------------------
// Epilogue: runs BEFORE gru each replay — zero barrier state + write outh.
// ---------------------------------------------------------------------------
__global__ void epilogue(const float* __restrict__ h0, float* __restrict__ dst)
{
    int i = blockIdx.x * blockDim.x + threadIdx.x;
    if (i < HH) dst[i] = h0[i];
    if (i < 16) g_leaf[i] = 0;
    if (i == 16) g_root = 0;
    if (i == 17) g_release = 0;
}

// ---------------------------------------------------------------------------
extern "C" void kernel_launch(void* const* d_in, const int* in_sizes, int n_in,
                              void* d_out, int out_size)
{
    const float* x = (const float*)d_in[0];
    const unsigned char* reset_raw = (const unsigned char*)d_in[1];
    const float* w_i = (const float*)d_in[2];
    const float* w_h = (const float*)d_in[3];
    const float* b = (const float*)d_in[4];
    const float* h0 = (const float*)d_in[5];

    float* out0 = (float*)d_out;
    float* out1 = out0 + (size_t)NB * TT * HH;
    float* outh = out1 + (size_t)NB * TT * HH;

    // smem: 98688 + 131072 + 2688 = 232448
    static const size_t SMEM = 24 * WPAD * 4 + 8192 * 16 + 672 * 4;
    cudaFuncSetAttribute(gru_persistent,
                         cudaFuncAttributeMaxDynamicSharedMemorySize, (int)SMEM);

    // 0) reset masks
    prep_reset<<<1, 512>>>(reset_raw);

    // 1) gates = x @ w_i + b
    {
        dim3 grid(GG / 128, (NB * TT) / 128);
        gemm_gates<<<grid, 256>>>(x, w_i, b);
    }

    // 2) barrier state reset + third output (safe before recurrence)
    epilogue<<<1, 1024>>>(h0, outh);

    // 3) full recurrence in ONE persistent kernel (last launch -> ncu slot)
    gru_persistent<<<NCTA, NTHR, SMEM>>>(w_h, h0, out0, out1);
}

// round 8
// speedup vs baseline: 1.0914x; 1.0914x over previous
#include <cuda_runtime.h>
#include <cstdint>

// Problem constants
#define NB 32      // batch
#define TT 512     // time steps
#define DD 512     // input dim
#define HH 1024    // hidden dim
#define GG 3072    // 3*H

#define NCTA 128   // persistent grid
#define NTHR 512

#define WPAD 1028  // padded weight column stride (floats)
#define WPAD4 257  // in float4 units

// Scratch (module-load allocated; no runtime alloc)
__device__ float g_gates[(size_t)NB * TT * GG];  // 16384 x 3072
__device__ float g_zr[NB * 2 * HH];              // 32 x 2048
__device__ unsigned g_rmask[TT];                 // per-step reset bitmasks

// Hierarchical barrier state (zeroed by epilogue BEFORE gru each replay)
__device__ unsigned g_leaf[16];
__device__ unsigned g_root;
__device__ unsigned g_release;

// packed f32x2 fma: acc = a*b + acc (each u64 = 2 packed floats)
#define FMA2(acc, a, b) \
    asm("fma.rn.f32x2 %0, %1, %2, %0;" : "+l"(acc) : "l"(a), "l"(b))

__device__ __forceinline__ unsigned long long dup2(float v)
{
    unsigned long long r;
    asm("mov.b64 %0, {%1, %1};" : "=l"(r) : "f"(v));
    return r;
}

__device__ __forceinline__ float sum2(unsigned long long v)
{
    float2 p = *reinterpret_cast<float2*>(&v);
    return p.x + p.y;
}

// ---------------------------------------------------------------------------
// Prep: detect reset dtype (bool8 vs int32), build per-step bitmasks.
// ---------------------------------------------------------------------------
__global__ void prep_reset(const unsigned char* __restrict__ raw)
{
    __shared__ int s_bool8;
    int tid = threadIdx.x;
    if (tid == 0) s_bool8 = 0;
    __syncthreads();
    for (int i = tid; i < 4096; i += blockDim.x)
        if ((i & 3) != 0 && raw[i] != 0) s_bool8 = 1;
    __syncthreads();
    bool b8 = (s_bool8 != 0);
    const int* r32 = (const int*)raw;
    for (int t = tid; t < TT; t += blockDim.x) {
        unsigned m = 0;
        for (int b = 0; b < NB; b++) {
            bool rv = b8 ? (raw[b * TT + t] != 0) : (r32[b * TT + t] != 0);
            if (rv) m |= (1u << b);
        }
        if (t == 0) m = 0xFFFFFFFFu;
        g_rmask[t] = m;
    }
}

// ---------------------------------------------------------------------------
// GEMM: gates = X(16384x512) @ Wi(512x3072) + bias   (f32x2 micro-kernel)
// ---------------------------------------------------------------------------
__global__ __launch_bounds__(256) void gemm_gates(
    const float* __restrict__ X, const float* __restrict__ Wi,
    const float* __restrict__ bias)
{
    const int K = DD;
    const int Nn = GG;

    __shared__ float As[8][128];
    __shared__ float Bs[8][128];

    const int bm = blockIdx.y * 128;
    const int bn = blockIdx.x * 128;
    const int tid = threadIdx.x;

    const int aRow = tid >> 1;
    const int aCol = (tid & 1) << 2;
    const int bRow = tid >> 5;
    const int bCol = (tid & 31) << 2;

    const int tRow = (tid >> 4) << 3;
    const int tCol = (tid & 15) << 3;

    unsigned long long acc2[8][4];
#pragma unroll
    for (int i = 0; i < 8; i++)
#pragma unroll
        for (int j = 0; j < 4; j++) acc2[i][j] = 0ull;

    for (int k0 = 0; k0 < K; k0 += 8) {
        float4 a4 = *reinterpret_cast<const float4*>(
            X + (size_t)(bm + aRow) * K + k0 + aCol);
        As[aCol + 0][aRow] = a4.x;
        As[aCol + 1][aRow] = a4.y;
        As[aCol + 2][aRow] = a4.z;
        As[aCol + 3][aRow] = a4.w;
        *reinterpret_cast<float4*>(&Bs[bRow][bCol]) =
            *reinterpret_cast<const float4*>(Wi + (size_t)(k0 + bRow) * Nn + bn + bCol);
        __syncthreads();

#pragma unroll
        for (int kk = 0; kk < 8; kk++) {
            float4 a0 = *reinterpret_cast<const float4*>(&As[kk][tRow]);
            float4 a1 = *reinterpret_cast<const float4*>(&As[kk][tRow + 4]);
            ulonglong2 b01 = *reinterpret_cast<const ulonglong2*>(&Bs[kk][tCol]);
            ulonglong2 b23 = *reinterpret_cast<const ulonglong2*>(&Bs[kk][tCol + 4]);
            float ar[8] = {a0.x, a0.y, a0.z, a0.w, a1.x, a1.y, a1.z, a1.w};
#pragma unroll
            for (int i = 0; i < 8; i++) {
                unsigned long long aa = dup2(ar[i]);
                FMA2(acc2[i][0], aa, b01.x);
                FMA2(acc2[i][1], aa, b01.y);
                FMA2(acc2[i][2], aa, b23.x);
                FMA2(acc2[i][3], aa, b23.y);
            }
        }
        __syncthreads();
    }

#pragma unroll
    for (int i = 0; i < 8; i++) {
#pragma unroll
        for (int j2 = 0; j2 < 4; j2 += 2) {
            unsigned long long v0 = acc2[i][j2];
            unsigned long long v1 = acc2[i][j2 + 1];
            float2 p0 = *reinterpret_cast<float2*>(&v0);
            float2 p1 = *reinterpret_cast<float2*>(&v1);
            int j = j2 * 2;
            float4 v;
            v.x = p0.x + bias[bn + tCol + j + 0];
            v.y = p0.y + bias[bn + tCol + j + 1];
            v.z = p1.x + bias[bn + tCol + j + 2];
            v.w = p1.y + bias[bn + tCol + j + 3];
            *reinterpret_cast<float4*>(
                g_gates + (size_t)(bm + tRow + i) * Nn + bn + tCol + j) = v;
        }
    }
}

extern __shared__ float dsm[];

// ---------------------------------------------------------------------------
// Persistent recurrence kernel (v5: 512 threads, 4-way k split, seq reduction)
// CTA x owns zr cols [16x,16x+16) and a cols [8x,8x+8), all 32 batches.
// smem: w_s 24 x 1028 floats (98688B) + hp4 8192 float4 (131072B) +
//       red 528 floats + aout 256 floats (tail 672 floats = 2688B) = 232448 B
// ---------------------------------------------------------------------------
__global__ __launch_bounds__(NTHR, 1) void gru_persistent(
    const float* __restrict__ w_h, const float* __restrict__ h0,
    float* out0, float* __restrict__ out1)
{
    float* w_s = dsm;                                  // 24*WPAD floats
    float4* hp4 = (float4*)(dsm + 24 * WPAD);          // 8192 float4
    float* red = dsm + 24 * WPAD + 32768;              // 528 floats (stride 33)
    float* aout = red + 288;                           // 256 floats (p2 only)

    const int x = blockIdx.x;
    const int tid = threadIdx.x;
    const int lane = tid & 31;
    const int wp = tid >> 5;
    const int leaf = x & 15;

    const int c_l = lane >> 3;     // 0..3 column lane
    const int b_l = lane & 7;      // 0..7 batch lane

    // phase1 warp coords: (kq, cg, bh)
    const int p1_kq = wp >> 2;
    const int p1_cg = (wp >> 1) & 1;
    const int p1_bh = wp & 1;
    const int p1_b0 = p1_bh * 16 + b_l;        // + 8
    const int p1_c0 = p1_cg * 8 + c_l;         // + 4
    const int p1_k0 = p1_kq * 64;

    // phase2 warp coords: (kq, bh, ch)
    const int p2_kq = wp >> 2;
    const int p2_bh = (wp >> 1) & 1;
    const int p2_ch = wp & 1;
    const int p2_b0 = p2_bh * 16 + b_l;        // + 8
    const int p2_c  = p2_ch * 4 + c_l;         // local a col 0..7
    const int p2_k0 = p2_kq * 64;

    // ---- one-time weight preload: w_s[c*WPAD + k] ----
    for (int i = tid; i < 24 * 1024; i += NTHR) {
        int c = i % 24;
        int k = i / 24;
        int gcol = (c < 16) ? (x * 16 + c) : (2048 + x * 8 + (c - 16));
        w_s[c * WPAD + k] = w_h[(size_t)k * GG + gcol];
    }
    __syncthreads();

    const float4* h0_4 = (const float4*)h0;
    const float4* out0_4 = (const float4*)out0;
    const float4* gzr4 = (const float4*)g_zr;
    const ulonglong2* hu2 = (const ulonglong2*)hp4;
    const ulonglong2* wu2 = (const ulonglong2*)w_s;
    const float4* aout4 = (const float4*)aout;

    // finalize-thread coords (tid < 64)
    const int f_b = tid >> 1;
    const int f_q = tid & 1;

    for (int t = 0; t < TT; t++) {
        // ---- independent prefetches (overlap with barrier-2 wait) ----
        float gx1[4];
        if (p1_kq == 0) {
            const float* gr0 = g_gates + ((size_t)p1_b0 * TT + t) * GG + x * 16;
            const float* gr1 = g_gates + ((size_t)(p1_b0 + 8) * TT + t) * GG + x * 16;
            gx1[0] = gr0[p1_c0];
            gx1[1] = gr0[p1_c0 + 4];
            gx1[2] = gr1[p1_c0];
            gx1[3] = gr1[p1_c0 + 4];
        }
        unsigned rm = g_rmask[t];
        int tp = (t > 0) ? (t - 1) : 0;

        // ---- wait for barrier 2 of previous step (h(t-1) ready) ----
        if (t > 0) {
            unsigned n = 2u * t;
            if (tid == 0) {
                while (*(volatile unsigned*)&g_release < n) __nanosleep(32);
                __threadfence();
            }
            __syncthreads();
        }

        // ---- stage h_eff (all 32 batches) into hp4, swizzled ----
        for (int i = tid; i < 8192; i += NTHR) {
            int b = i >> 8;
            int k4 = i & 255;
            float4 v;
            if ((rm >> b) & 1u)
                v = h0_4[k4];
            else
                v = __ldcg(&out0_4[((size_t)b * TT + tp) * 256 + k4]);
            hp4[b * 256 + (k4 ^ (b & 7))] = v;
        }
        __syncthreads();

        // ---- phase1 FMA: 2b x 2c register tile, quarter-k per warp ----
        {
            unsigned long long a00 = 0, a01 = 0, a10 = 0, a11 = 0;
            const ulonglong2* hA = hu2 + p1_b0 * 256;
            const ulonglong2* hB = hu2 + (p1_b0 + 8) * 256;
            const ulonglong2* wA = wu2 + p1_c0 * WPAD4;
            const ulonglong2* wB = wA + 4 * WPAD4;
#pragma unroll 4
            for (int k4 = p1_k0; k4 < p1_k0 + 64; ++k4) {
                int hk = k4 ^ b_l;
                ulonglong2 hv0 = hA[hk];
                ulonglong2 hv1 = hB[hk];
                ulonglong2 wv0 = wA[k4];
                ulonglong2 wv1 = wB[k4];
                FMA2(a00, hv0.x, wv0.x); FMA2(a00, hv0.y, wv0.y);
                FMA2(a01, hv0.x, wv1.x); FMA2(a01, hv0.y, wv1.y);
                FMA2(a10, hv1.x, wv0.x); FMA2(a10, hv1.y, wv0.y);
                FMA2(a11, hv1.x, wv1.x); FMA2(a11, hv1.y, wv1.y);
            }
            float m0 = sum2(a00), m1 = sum2(a01);
            float m2 = sum2(a10), m3 = sum2(a11);

            // sequential 3-round k reduction into kq==0
#pragma unroll
            for (int r = 1; r <= 3; r++) {
                if (p1_kq == r) {
                    red[(p1_c0)     * 33 + p1_b0]     = m0;
                    red[(p1_c0 + 4) * 33 + p1_b0]     = m1;
                    red[(p1_c0)     * 33 + p1_b0 + 8] = m2;
                    red[(p1_c0 + 4) * 33 + p1_b0 + 8] = m3;
                }
                __syncthreads();
                if (p1_kq == 0) {
                    m0 += red[(p1_c0)     * 33 + p1_b0];
                    m1 += red[(p1_c0 + 4) * 33 + p1_b0];
                    m2 += red[(p1_c0)     * 33 + p1_b0 + 8];
                    m3 += red[(p1_c0 + 4) * 33 + p1_b0 + 8];
                }
                __syncthreads();
            }
            if (p1_kq == 0) {
                float* z0 = g_zr + p1_b0 * 2048 + x * 16;
                float* z1 = g_zr + (p1_b0 + 8) * 2048 + x * 16;
                z0[p1_c0]     = 1.0f / (1.0f + __expf(-(gx1[0] + m0)));
                z0[p1_c0 + 4] = 1.0f / (1.0f + __expf(-(gx1[1] + m1)));
                z1[p1_c0]     = 1.0f / (1.0f + __expf(-(gx1[2] + m2)));
                z1[p1_c0 + 4] = 1.0f / (1.0f + __expf(-(gx1[3] + m3)));
            }
        }

        // ---- barrier 1 arrive (zr ready) ----
        unsigned n1 = 2u * t + 1u;
        __syncthreads();
        if (tid == 0) {
            __threadfence();
            unsigned o = atomicAdd(&g_leaf[leaf], 1u);
            if (o == n1 * 8u - 1u) {
                unsigned o2 = atomicAdd(&g_root, 1u);
                if (o2 == n1 * 16u - 1u) atomicExch(&g_release, n1);
            }
        }

        // ---- overlap: prefetch local data while waiting ----
        float gx2a = 0.f, gx2b = 0.f;
        if (p2_kq == 0) {
            const float* ga = g_gates + ((size_t)p2_b0 * TT + t) * GG + 2048 + x * 8;
            const float* gb = g_gates + ((size_t)(p2_b0 + 8) * TT + t) * GG + 2048 + x * 8;
            gx2a = ga[p2_c];
            gx2b = gb[p2_c];
        }
        float4 hown;
        if (tid < 64)
            hown = hp4[f_b * 256 + ((x * 2 + f_q) ^ (f_b & 7))];

        // ---- barrier 1 wait ----
        if (tid == 0) {
            while (*(volatile unsigned*)&g_release < n1) __nanosleep(32);
            __threadfence();
        }
        __syncthreads();

        float4 z4;
        if (tid < 64)
            z4 = __ldcg(&gzr4[f_b * 512 + x * 2 + f_q]);

        // ---- stage rh = r * h in place ----
        for (int i = tid; i < 8192; i += NTHR) {
            int b = i >> 8;
            int k4 = i & 255;
            int sidx = b * 256 + (k4 ^ (b & 7));
            float4 h = hp4[sidx];
            float4 r = __ldcg(&gzr4[b * 512 + 256 + k4]);
            h.x *= r.x; h.y *= r.y; h.z *= r.z; h.w *= r.w;
            hp4[sidx] = h;
        }
        __syncthreads();

        // ---- phase2 FMA: 2b x 1c register tile, quarter-k per warp ----
        {
            unsigned long long a0 = 0, a1 = 0;
            const ulonglong2* hA = hu2 + p2_b0 * 256;
            const ulonglong2* hB = hu2 + (p2_b0 + 8) * 256;
            const ulonglong2* wA = wu2 + (16 + p2_c) * WPAD4;
#pragma unroll 4
            for (int k4 = p2_k0; k4 < p2_k0 + 64; ++k4) {
                int hk = k4 ^ b_l;
                ulonglong2 hv0 = hA[hk];
                ulonglong2 hv1 = hB[hk];
                ulonglong2 wv = wA[k4];
                FMA2(a0, hv0.x, wv.x); FMA2(a0, hv0.y, wv.y);
                FMA2(a1, hv1.x, wv.x); FMA2(a1, hv1.y, wv.y);
            }
            float m0 = sum2(a0), m1 = sum2(a1);

#pragma unroll
            for (int r = 1; r <= 3; r++) {
                if (p2_kq == r) {
                    red[p2_c * 33 + p2_b0]     = m0;
                    red[p2_c * 33 + p2_b0 + 8] = m1;
                }
                __syncthreads();
                if (p2_kq == 0) {
                    m0 += red[p2_c * 33 + p2_b0];
                    m1 += red[p2_c * 33 + p2_b0 + 8];
                }
                __syncthreads();
            }
            if (p2_kq == 0) {
                aout[p2_b0 * 8 + p2_c]       = tanhf(gx2a + m0);
                aout[(p2_b0 + 8) * 8 + p2_c] = tanhf(gx2b + m1);
            }
            __syncthreads();
        }

        // ---- finalize: h_next = (1-z)h + z*a, write both outputs ----
        if (tid < 64) {
            float4 av = aout4[tid];
            float4 hn;
            hn.x = (1.0f - z4.x) * hown.x + z4.x * av.x;
            hn.y = (1.0f - z4.y) * hown.y + z4.y * av.y;
            hn.z = (1.0f - z4.z) * hown.z + z4.z * av.z;
            hn.w = (1.0f - z4.w) * hown.w + z4.w * av.w;
            size_t o4 = ((size_t)f_b * TT + t) * 256 + x * 2 + f_q;
            ((float4*)out0)[o4] = hn;
            ((float4*)out1)[o4] = hn;
        }

        // ---- barrier 2 arrive (h(t) ready); wait at next loop top ----
        unsigned n2 = 2u * t + 2u;
        __syncthreads();
        if (tid == 0) {
            __threadfence();
            unsigned o = atomicAdd(&g_leaf[leaf], 1u);
            if (o == n2 * 8u - 1u) {
                unsigned o2 = atomicAdd(&g_root, 1u);
                if (o2 == n2 * 16u - 1u) atomicExch(&g_release, n2);
            }
        }
    }
}

// ---------------------------------------------------------------------------
// Epilogue: runs BEFORE gru each replay — zero barrier state + write outh.
// ---------------------------------------------------------------------------
__global__ void epilogue(const float* __restrict__ h0, float* __restrict__ dst)
{
    int i = blockIdx.x * blockDim.x + threadIdx.x;
    if (i < HH) dst[i] = h0[i];
    if (i < 16) g_leaf[i] = 0;
    if (i == 16) g_root = 0;
    if (i == 17) g_release = 0;
}

// ---------------------------------------------------------------------------
extern "C" void kernel_launch(void* const* d_in, const int* in_sizes, int n_in,
                              void* d_out, int out_size)
{
    const float* x = (const float*)d_in[0];
    const unsigned char* reset_raw = (const unsigned char*)d_in[1];
    const float* w_i = (const float*)d_in[2];
    const float* w_h = (const float*)d_in[3];
    const float* b = (const float*)d_in[4];
    const float* h0 = (const float*)d_in[5];

    float* out0 = (float*)d_out;
    float* out1 = out0 + (size_t)NB * TT * HH;
    float* outh = out1 + (size_t)NB * TT * HH;

    // smem: 98688 + 131072 + 2688 = 232448
    static const size_t SMEM = 24 * WPAD * 4 + 8192 * 16 + 672 * 4;
    cudaFuncSetAttribute(gru_persistent,
                         cudaFuncAttributeMaxDynamicSharedMemorySize, (int)SMEM);

    // 0) reset masks
    prep_reset<<<1, 512>>>(reset_raw);

    // 1) gates = x @ w_i + b
    {
        dim3 grid(GG / 128, (NB * TT) / 128);
        gemm_gates<<<grid, 256>>>(x, w_i, b);
    }

    // 2) barrier state reset + third output (safe before recurrence)
    epilogue<<<1, 1024>>>(h0, outh);

    // 3) full recurrence in ONE persistent kernel (last launch -> ncu slot)
    gru_persistent<<<NCTA, NTHR, SMEM>>>(w_h, h0, out0, out1);
}

// round 10
// speedup vs baseline: 1.1555x; 1.0588x over previous
#include <cuda_runtime.h>
#include <cuda_bf16.h>
#include <cstdint>

// Problem constants
#define NB 32      // batch
#define TT 512     // time steps
#define DD 512     // input dim
#define HH 1024    // hidden dim
#define GG 3072    // 3*H

#define NCTA 128   // persistent grid
#define NTHR 512

#define WPAD 1028  // padded weight column stride (floats)
#define WPAD4 257  // in float4 units

// Scratch (module-load allocated; no runtime alloc)
__device__ float g_gates[(size_t)NB * TT * GG];  // 16384 x 3072
__device__ float g_zr[NB * 2 * HH];              // 32 x 2048
__device__ unsigned g_rmask[TT];                 // per-step reset bitmasks

// split-precision bf16 operands for the gates GEMM
__device__ __nv_bfloat16 g_xhi[(size_t)NB * TT * DD];
__device__ __nv_bfloat16 g_xlo[(size_t)NB * TT * DD];
__device__ __nv_bfloat16 g_whi[(size_t)GG * DD];   // transposed [n][k]
__device__ __nv_bfloat16 g_wlo[(size_t)GG * DD];

// Hierarchical barrier state (zeroed by epilogue BEFORE gru each replay)
__device__ unsigned g_leaf[16];
__device__ unsigned g_root;
__device__ unsigned g_release;

// packed f32x2 fma: acc = a*b + acc (each u64 = 2 packed floats)
#define FMA2(acc, a, b) \
    asm("fma.rn.f32x2 %0, %1, %2, %0;" : "+l"(acc) : "l"(a), "l"(b))

__device__ __forceinline__ float sum2(unsigned long long v)
{
    float2 p = *reinterpret_cast<float2*>(&v);
    return p.x + p.y;
}

__device__ __forceinline__ uint32_t smem_u32(const void* p)
{
    uint32_t a;
    asm("{ .reg .u64 t; cvta.to.shared.u64 t, %1; cvt.u32.u64 %0, t; }"
        : "=r"(a) : "l"(p));
    return a;
}

// ldmatrix x4 (four 8x8 b16 tiles)
#define LDSM_X4(r, a) \
    asm volatile("ldmatrix.sync.aligned.m8n8.x4.shared.b16 {%0,%1,%2,%3}, [%4];" \
        : "=r"((r)[0]), "=r"((r)[1]), "=r"((r)[2]), "=r"((r)[3]) : "r"(a))

// bf16 m16n8k16 mma, f32 accum
#define MMA_BF16(c, a, b0, b1) \
    asm volatile("mma.sync.aligned.m16n8k16.row.col.f32.bf16.bf16.f32 " \
        "{%0,%1,%2,%3}, {%4,%5,%6,%7}, {%8,%9}, {%0,%1,%2,%3};" \
        : "+f"((c)[0]), "+f"((c)[1]), "+f"((c)[2]), "+f"((c)[3]) \
        : "r"((a)[0]), "r"((a)[1]), "r"((a)[2]), "r"((a)[3]), "r"(b0), "r"(b1))

// ---------------------------------------------------------------------------
// Prep: detect reset dtype (bool8 vs int32), build per-step bitmasks.
// ---------------------------------------------------------------------------
__global__ void prep_reset(const unsigned char* __restrict__ raw)
{
    __shared__ int s_bool8;
    int tid = threadIdx.x;
    if (tid == 0) s_bool8 = 0;
    __syncthreads();
    for (int i = tid; i < 4096; i += blockDim.x)
        if ((i & 3) != 0 && raw[i] != 0) s_bool8 = 1;
    __syncthreads();
    bool b8 = (s_bool8 != 0);
    const int* r32 = (const int*)raw;
    for (int t = tid; t < TT; t += blockDim.x) {
        unsigned m = 0;
        for (int b = 0; b < NB; b++) {
            bool rv = b8 ? (raw[b * TT + t] != 0) : (r32[b * TT + t] != 0);
            if (rv) m |= (1u << b);
        }
        if (t == 0) m = 0xFFFFFFFFu;
        g_rmask[t] = m;
    }
}

// ---------------------------------------------------------------------------
// Split-precision conversion kernels
// ---------------------------------------------------------------------------
__global__ void conv_x(const float* __restrict__ x)
{
    int i = blockIdx.x * blockDim.x + threadIdx.x;
    if (i < NB * TT * DD) {
        float v = x[i];
        __nv_bfloat16 h = __float2bfloat16(v);
        g_xhi[i] = h;
        g_xlo[i] = __float2bfloat16(v - __bfloat162float(h));
    }
}

__global__ void conv_w(const float* __restrict__ w)
{
    int i = blockIdx.x * blockDim.x + threadIdx.x;   // over 512*3072
    if (i < DD * GG) {
        int k = i / GG;
        int n = i % GG;
        float v = w[i];
        __nv_bfloat16 h = __float2bfloat16(v);
        g_whi[(size_t)n * DD + k] = h;
        g_wlo[(size_t)n * DD + k] = __float2bfloat16(v - __bfloat162float(h));
    }
}

// ---------------------------------------------------------------------------
// Tensor-core gates GEMM (mma.sync bf16, split precision, f32 accum)
// gates[16384,3072] = x @ w_i + bias
// grid (24, 128), 256 threads (8 warps: 2m x 4n). Tile 128m x 128n x 32k.
// ---------------------------------------------------------------------------
#define ASTR 40   // smem row stride in bf16 (32 + 8 pad)

__global__ __launch_bounds__(256) void mma_gates(const float* __restrict__ bias)
{
    __shared__ __nv_bfloat16 sAh[128][ASTR];
    __shared__ __nv_bfloat16 sAl[128][ASTR];
    __shared__ __nv_bfloat16 sBh[128][ASTR];
    __shared__ __nv_bfloat16 sBl[128][ASTR];

    const int tid = threadIdx.x;
    const int lane = tid & 31;
    const int wid = tid >> 5;
    const int wm = wid & 1;        // 2 warps over m (64 rows each)
    const int wn = wid >> 1;       // 4 warps over n (32 cols each)
    const int bn = blockIdx.x * 128;
    const int bm = blockIdx.y * 128;

    float c[4][4][4];
#pragma unroll
    for (int i = 0; i < 4; i++)
#pragma unroll
        for (int j = 0; j < 4; j++)
#pragma unroll
            for (int q = 0; q < 4; q++) c[i][j][q] = 0.0f;

    // per-thread ldmatrix source coordinates
    const int a_row = wm * 64 + (lane & 7) + ((lane >> 3) & 1) * 8;   // + mi*16
    const int a_col = ((lane >> 4) & 1) * 8;                          // + k0
    const int b_row = wn * 32 + (lane & 7) + ((lane >> 4) & 1) * 8;   // + j*16
    const int b_col = ((lane >> 3) & 1) * 8;                          // + k0

    for (int kc = 0; kc < 16; kc++) {
        // ---- global -> smem: A 128x32 (hi/lo), B 128x32 (hi/lo) ----
        for (int i = tid; i < 512; i += 256) {
            int row = i >> 2;
            int c8 = (i & 3) * 8;
            size_t ga = (size_t)(bm + row) * DD + kc * 32 + c8;
            size_t gb = (size_t)(bn + row) * DD + kc * 32 + c8;
            *(uint4*)&sAh[row][c8] = *(const uint4*)&g_xhi[ga];
            *(uint4*)&sAl[row][c8] = *(const uint4*)&g_xlo[ga];
            *(uint4*)&sBh[row][c8] = *(const uint4*)&g_whi[gb];
            *(uint4*)&sBl[row][c8] = *(const uint4*)&g_wlo[gb];
        }
        __syncthreads();

#pragma unroll
        for (int ks = 0; ks < 2; ks++) {
            const int k0 = ks * 16;
            uint32_t ah[4][4], al[4][4], bh[2][4], bl[2][4];
#pragma unroll
            for (int mi = 0; mi < 4; mi++) {
                uint32_t adr = smem_u32(
                    &sAh[a_row + mi * 16][k0 + a_col]);
                LDSM_X4(ah[mi], adr);
                adr = smem_u32(&sAl[a_row + mi * 16][k0 + a_col]);
                LDSM_X4(al[mi], adr);
            }
#pragma unroll
            for (int j = 0; j < 2; j++) {
                uint32_t adr = smem_u32(
                    &sBh[b_row + j * 16][k0 + b_col]);
                LDSM_X4(bh[j], adr);
                adr = smem_u32(&sBl[b_row + j * 16][k0 + b_col]);
                LDSM_X4(bl[j], adr);
            }
#pragma unroll
            for (int mi = 0; mi < 4; mi++) {
#pragma unroll
                for (int nj = 0; nj < 4; nj++) {
                    int j = nj >> 1, p = (nj & 1) * 2;
                    MMA_BF16(c[mi][nj], ah[mi], bh[j][p], bh[j][p + 1]);
                    MMA_BF16(c[mi][nj], ah[mi], bl[j][p], bl[j][p + 1]);
                    MMA_BF16(c[mi][nj], al[mi], bh[j][p], bh[j][p + 1]);
                }
            }
        }
        __syncthreads();
    }

    // ---- epilogue: bias add + store ----
#pragma unroll
    for (int mi = 0; mi < 4; mi++) {
#pragma unroll
        for (int nj = 0; nj < 4; nj++) {
            int r = bm + wm * 64 + mi * 16 + (lane >> 2);
            int cn = bn + wn * 32 + nj * 8 + (lane & 3) * 2;
            float b0 = bias[cn], b1 = bias[cn + 1];
            float2 v0 = make_float2(c[mi][nj][0] + b0, c[mi][nj][1] + b1);
            float2 v1 = make_float2(c[mi][nj][2] + b0, c[mi][nj][3] + b1);
            *(float2*)&g_gates[(size_t)r * GG + cn] = v0;
            *(float2*)&g_gates[(size_t)(r + 8) * GG + cn] = v1;
        }
    }
}

extern __shared__ float dsm[];

// ---------------------------------------------------------------------------
// Persistent recurrence kernel — unchanged from proven R8 version (v5)
// ---------------------------------------------------------------------------
__global__ __launch_bounds__(NTHR, 1) void gru_persistent(
    const float* __restrict__ w_h, const float* __restrict__ h0,
    float* out0, float* __restrict__ out1)
{
    float* w_s = dsm;                                  // 24*WPAD floats
    float4* hp4 = (float4*)(dsm + 24 * WPAD);          // 8192 float4
    float* red = dsm + 24 * WPAD + 32768;              // 528 floats (stride 33)
    float* aout = red + 288;                           // 256 floats (p2 only)

    const int x = blockIdx.x;
    const int tid = threadIdx.x;
    const int lane = tid & 31;
    const int wp = tid >> 5;
    const int leaf = x & 15;

    const int c_l = lane >> 3;
    const int b_l = lane & 7;

    const int p1_kq = wp >> 2;
    const int p1_cg = (wp >> 1) & 1;
    const int p1_bh = wp & 1;
    const int p1_b0 = p1_bh * 16 + b_l;
    const int p1_c0 = p1_cg * 8 + c_l;
    const int p1_k0 = p1_kq * 64;

    const int p2_kq = wp >> 2;
    const int p2_bh = (wp >> 1) & 1;
    const int p2_ch = wp & 1;
    const int p2_b0 = p2_bh * 16 + b_l;
    const int p2_c  = p2_ch * 4 + c_l;
    const int p2_k0 = p2_kq * 64;

    for (int i = tid; i < 24 * 1024; i += NTHR) {
        int c = i % 24;
        int k = i / 24;
        int gcol = (c < 16) ? (x * 16 + c) : (2048 + x * 8 + (c - 16));
        w_s[c * WPAD + k] = w_h[(size_t)k * GG + gcol];
    }
    __syncthreads();

    const float4* h0_4 = (const float4*)h0;
    const float4* out0_4 = (const float4*)out0;
    const float4* gzr4 = (const float4*)g_zr;
    const ulonglong2* hu2 = (const ulonglong2*)hp4;
    const ulonglong2* wu2 = (const ulonglong2*)w_s;
    const float4* aout4 = (const float4*)aout;

    const int f_b = tid >> 1;
    const int f_q = tid & 1;

    for (int t = 0; t < TT; t++) {
        float gx1[4];
        if (p1_kq == 0) {
            const float* gr0 = g_gates + ((size_t)p1_b0 * TT + t) * GG + x * 16;
            const float* gr1 = g_gates + ((size_t)(p1_b0 + 8) * TT + t) * GG + x * 16;
            gx1[0] = gr0[p1_c0];
            gx1[1] = gr0[p1_c0 + 4];
            gx1[2] = gr1[p1_c0];
            gx1[3] = gr1[p1_c0 + 4];
        }
        unsigned rm = g_rmask[t];
        int tp = (t > 0) ? (t - 1) : 0;

        if (t > 0) {
            unsigned n = 2u * t;
            if (tid == 0) {
                while (*(volatile unsigned*)&g_release < n) __nanosleep(32);
                __threadfence();
            }
            __syncthreads();
        }

        for (int i = tid; i < 8192; i += NTHR) {
            int b = i >> 8;
            int k4 = i & 255;
            float4 v;
            if ((rm >> b) & 1u)
                v = h0_4[k4];
            else
                v = __ldcg(&out0_4[((size_t)b * TT + tp) * 256 + k4]);
            hp4[b * 256 + (k4 ^ (b & 7))] = v;
        }
        __syncthreads();

        {
            unsigned long long a00 = 0, a01 = 0, a10 = 0, a11 = 0;
            const ulonglong2* hA = hu2 + p1_b0 * 256;
            const ulonglong2* hB = hu2 + (p1_b0 + 8) * 256;
            const ulonglong2* wA = wu2 + p1_c0 * WPAD4;
            const ulonglong2* wB = wA + 4 * WPAD4;
#pragma unroll 4
            for (int k4 = p1_k0; k4 < p1_k0 + 64; ++k4) {
                int hk = k4 ^ b_l;
                ulonglong2 hv0 = hA[hk];
                ulonglong2 hv1 = hB[hk];
                ulonglong2 wv0 = wA[k4];
                ulonglong2 wv1 = wB[k4];
                FMA2(a00, hv0.x, wv0.x); FMA2(a00, hv0.y, wv0.y);
                FMA2(a01, hv0.x, wv1.x); FMA2(a01, hv0.y, wv1.y);
                FMA2(a10, hv1.x, wv0.x); FMA2(a10, hv1.y, wv0.y);
                FMA2(a11, hv1.x, wv1.x); FMA2(a11, hv1.y, wv1.y);
            }
            float m0 = sum2(a00), m1 = sum2(a01);
            float m2 = sum2(a10), m3 = sum2(a11);

#pragma unroll
            for (int r = 1; r <= 3; r++) {
                if (p1_kq == r) {
                    red[(p1_c0)     * 33 + p1_b0]     = m0;
                    red[(p1_c0 + 4) * 33 + p1_b0]     = m1;
                    red[(p1_c0)     * 33 + p1_b0 + 8] = m2;
                    red[(p1_c0 + 4) * 33 + p1_b0 + 8] = m3;
                }
                __syncthreads();
                if (p1_kq == 0) {
                    m0 += red[(p1_c0)     * 33 + p1_b0];
                    m1 += red[(p1_c0 + 4) * 33 + p1_b0];
                    m2 += red[(p1_c0)     * 33 + p1_b0 + 8];
                    m3 += red[(p1_c0 + 4) * 33 + p1_b0 + 8];
                }
                __syncthreads();
            }
            if (p1_kq == 0) {
                float* z0 = g_zr + p1_b0 * 2048 + x * 16;
                float* z1 = g_zr + (p1_b0 + 8) * 2048 + x * 16;
                z0[p1_c0]     = 1.0f / (1.0f + __expf(-(gx1[0] + m0)));
                z0[p1_c0 + 4] = 1.0f / (1.0f + __expf(-(gx1[1] + m1)));
                z1[p1_c0]     = 1.0f / (1.0f + __expf(-(gx1[2] + m2)));
                z1[p1_c0 + 4] = 1.0f / (1.0f + __expf(-(gx1[3] + m3)));
            }
        }

        unsigned n1 = 2u * t + 1u;
        __syncthreads();
        if (tid == 0) {
            __threadfence();
            unsigned o = atomicAdd(&g_leaf[leaf], 1u);
            if (o == n1 * 8u - 1u) {
                unsigned o2 = atomicAdd(&g_root, 1u);
                if (o2 == n1 * 16u - 1u) atomicExch(&g_release, n1);
            }
        }

        float gx2a = 0.f, gx2b = 0.f;
        if (p2_kq == 0) {
            const float* ga = g_gates + ((size_t)p2_b0 * TT + t) * GG + 2048 + x * 8;
            const float* gb = g_gates + ((size_t)(p2_b0 + 8) * TT + t) * GG + 2048 + x * 8;
            gx2a = ga[p2_c];
            gx2b = gb[p2_c];
        }
        float4 hown;
        if (tid < 64)
            hown = hp4[f_b * 256 + ((x * 2 + f_q) ^ (f_b & 7))];

        if (tid == 0) {
            while (*(volatile unsigned*)&g_release < n1) __nanosleep(32);
            __threadfence();
        }
        __syncthreads();

        float4 z4;
        if (tid < 64)
            z4 = __ldcg(&gzr4[f_b * 512 + x * 2 + f_q]);

        for (int i = tid; i < 8192; i += NTHR) {
            int b = i >> 8;
            int k4 = i & 255;
            int sidx = b * 256 + (k4 ^ (b & 7));
            float4 h = hp4[sidx];
            float4 r = __ldcg(&gzr4[b * 512 + 256 + k4]);
            h.x *= r.x; h.y *= r.y; h.z *= r.z; h.w *= r.w;
            hp4[sidx] = h;
        }
        __syncthreads();

        {
            unsigned long long a0 = 0, a1 = 0;
            const ulonglong2* hA = hu2 + p2_b0 * 256;
            const ulonglong2* hB = hu2 + (p2_b0 + 8) * 256;
            const ulonglong2* wA = wu2 + (16 + p2_c) * WPAD4;
#pragma unroll 4
            for (int k4 = p2_k0; k4 < p2_k0 + 64; ++k4) {
                int hk = k4 ^ b_l;
                ulonglong2 hv0 = hA[hk];
                ulonglong2 hv1 = hB[hk];
                ulonglong2 wv = wA[k4];
                FMA2(a0, hv0.x, wv.x); FMA2(a0, hv0.y, wv.y);
                FMA2(a1, hv1.x, wv.x); FMA2(a1, hv1.y, wv.y);
            }
            float m0 = sum2(a0), m1 = sum2(a1);

#pragma unroll
            for (int r = 1; r <= 3; r++) {
                if (p2_kq == r) {
                    red[p2_c * 33 + p2_b0]     = m0;
                    red[p2_c * 33 + p2_b0 + 8] = m1;
                }
                __syncthreads();
                if (p2_kq == 0) {
                    m0 += red[p2_c * 33 + p2_b0];
                    m1 += red[p2_c * 33 + p2_b0 + 8];
                }
                __syncthreads();
            }
            if (p2_kq == 0) {
                aout[p2_b0 * 8 + p2_c]       = tanhf(gx2a + m0);
                aout[(p2_b0 + 8) * 8 + p2_c] = tanhf(gx2b + m1);
            }
            __syncthreads();
        }

        if (tid < 64) {
            float4 av = aout4[tid];
            float4 hn;
            hn.x = (1.0f - z4.x) * hown.x + z4.x * av.x;
            hn.y = (1.0f - z4.y) * hown.y + z4.y * av.y;
            hn.z = (1.0f - z4.z) * hown.z + z4.z * av.z;
            hn.w = (1.0f - z4.w) * hown.w + z4.w * av.w;
            size_t o4 = ((size_t)f_b * TT + t) * 256 + x * 2 + f_q;
            ((float4*)out0)[o4] = hn;
            ((float4*)out1)[o4] = hn;
        }

        unsigned n2 = 2u * t + 2u;
        __syncthreads();
        if (tid == 0) {
            __threadfence();
            unsigned o = atomicAdd(&g_leaf[leaf], 1u);
            if (o == n2 * 8u - 1u) {
                unsigned o2 = atomicAdd(&g_root, 1u);
                if (o2 == n2 * 16u - 1u) atomicExch(&g_release, n2);
            }
        }
    }
}

// ---------------------------------------------------------------------------
// Epilogue: runs BEFORE gru each replay — zero barrier state + write outh.
// ---------------------------------------------------------------------------
__global__ void epilogue(const float* __restrict__ h0, float* __restrict__ dst)
{
    int i = blockIdx.x * blockDim.x + threadIdx.x;
    if (i < HH) dst[i] = h0[i];
    if (i < 16) g_leaf[i] = 0;
    if (i == 16) g_root = 0;
    if (i == 17) g_release = 0;
}

// ---------------------------------------------------------------------------
extern "C" void kernel_launch(void* const* d_in, const int* in_sizes, int n_in,
                              void* d_out, int out_size)
{
    const float* x = (const float*)d_in[0];
    const unsigned char* reset_raw = (const unsigned char*)d_in[1];
    const float* w_i = (const float*)d_in[2];
    const float* w_h = (const float*)d_in[3];
    const float* b = (const float*)d_in[4];
    const float* h0 = (const float*)d_in[5];

    float* out0 = (float*)d_out;
    float* out1 = out0 + (size_t)NB * TT * HH;
    float* outh = out1 + (size_t)NB * TT * HH;

    static const size_t SMEM_GRU = 24 * WPAD * 4 + 8192 * 16 + 672 * 4;  // 232448
    cudaFuncSetAttribute(gru_persistent,
                         cudaFuncAttributeMaxDynamicSharedMemorySize, (int)SMEM_GRU);

    // 0) reset masks + split-precision conversion
    prep_reset<<<1, 512>>>(reset_raw);
    conv_x<<<(NB * TT * DD + 255) / 256, 256>>>(x);
    conv_w<<<(DD * GG + 255) / 256, 256>>>(w_i);

    // 1) gates = x @ w_i + b via mma.sync bf16 (split precision, f32 accum)
    {
        dim3 grid(GG / 128, (NB * TT) / 128);
        mma_gates<<<grid, 256>>>(b);
    }

    // 2) barrier state reset + third output
    epilogue<<<1, 1024>>>(h0, outh);

    // 3) full recurrence in ONE persistent kernel
    gru_persistent<<<NCTA, NTHR, SMEM_GRU>>>(w_h, h0, out0, out1);
}

// round 11
// speedup vs baseline: 1.6571x; 1.4340x over previous
#include <cuda_runtime.h>
#include <cuda_bf16.h>
#include <cstdint>

// Problem constants
#define NB 32      // batch
#define TT 512     // time steps
#define DD 512     // input dim
#define HH 1024    // hidden dim
#define GG 3072    // 3*H

#define NCTA 128   // persistent grid
#define NTHR 512

// Scratch (module-load allocated; no runtime alloc)
__device__ float g_gates[(size_t)NB * TT * GG];  // 16384 x 3072
__device__ float g_zr[NB * 2 * HH];              // 32 x 2048
__device__ unsigned g_rmask[TT];                 // per-step reset bitmasks

// split-precision bf16 operands for the gates GEMM
__device__ __nv_bfloat16 g_xhi[(size_t)NB * TT * DD];
__device__ __nv_bfloat16 g_xlo[(size_t)NB * TT * DD];
__device__ __nv_bfloat16 g_whi[(size_t)GG * DD];   // transposed [n][k]
__device__ __nv_bfloat16 g_wlo[(size_t)GG * DD];

// Hierarchical barrier state (zeroed by epilogue BEFORE gru each replay)
__device__ unsigned g_leaf[16];
__device__ unsigned g_root;
__device__ unsigned g_release;

// packed f32x2 fma (gates kernel only)
#define FMA2(acc, a, b) \
    asm("fma.rn.f32x2 %0, %1, %2, %0;" : "+l"(acc) : "l"(a), "l"(b))

__device__ __forceinline__ uint32_t smem_u32(const void* p)
{
    uint32_t a;
    asm("{ .reg .u64 t; cvta.to.shared.u64 t, %1; cvt.u32.u64 %0, t; }"
        : "=r"(a) : "l"(p));
    return a;
}

// ldmatrix x4 (four 8x8 b16 tiles)
#define LDSM_X4(r, a) \
    asm volatile("ldmatrix.sync.aligned.m8n8.x4.shared.b16 {%0,%1,%2,%3}, [%4];" \
        : "=r"((r)[0]), "=r"((r)[1]), "=r"((r)[2]), "=r"((r)[3]) : "r"(a))

// bf16 m16n8k16 mma, f32 accum
#define MMA_BF16(c, a, b0, b1) \
    asm volatile("mma.sync.aligned.m16n8k16.row.col.f32.bf16.bf16.f32 " \
        "{%0,%1,%2,%3}, {%4,%5,%6,%7}, {%8,%9}, {%0,%1,%2,%3};" \
        : "+f"((c)[0]), "+f"((c)[1]), "+f"((c)[2]), "+f"((c)[3]) \
        : "r"((a)[0]), "r"((a)[1]), "r"((a)[2]), "r"((a)[3]), "r"(b0), "r"(b1))

// split one float4 into hi/lo bf16 pairs (packed uints)
__device__ __forceinline__ void split4(float4 v, uint2& hi, uint2& lo)
{
    __nv_bfloat162 h01 = __floats2bfloat162_rn(v.x, v.y);
    __nv_bfloat162 h23 = __floats2bfloat162_rn(v.z, v.w);
    float2 f01 = __bfloat1622float2(h01);
    float2 f23 = __bfloat1622float2(h23);
    __nv_bfloat162 l01 = __floats2bfloat162_rn(v.x - f01.x, v.y - f01.y);
    __nv_bfloat162 l23 = __floats2bfloat162_rn(v.z - f23.x, v.w - f23.y);
    hi.x = *(uint32_t*)&h01; hi.y = *(uint32_t*)&h23;
    lo.x = *(uint32_t*)&l01; lo.y = *(uint32_t*)&l23;
}

// ---------------------------------------------------------------------------
// Prep: detect reset dtype (bool8 vs int32), build per-step bitmasks.
// ---------------------------------------------------------------------------
__global__ void prep_reset(const unsigned char* __restrict__ raw)
{
    __shared__ int s_bool8;
    int tid = threadIdx.x;
    if (tid == 0) s_bool8 = 0;
    __syncthreads();
    for (int i = tid; i < 4096; i += blockDim.x)
        if ((i & 3) != 0 && raw[i] != 0) s_bool8 = 1;
    __syncthreads();
    bool b8 = (s_bool8 != 0);
    const int* r32 = (const int*)raw;
    for (int t = tid; t < TT; t += blockDim.x) {
        unsigned m = 0;
        for (int b = 0; b < NB; b++) {
            bool rv = b8 ? (raw[b * TT + t] != 0) : (r32[b * TT + t] != 0);
            if (rv) m |= (1u << b);
        }
        if (t == 0) m = 0xFFFFFFFFu;
        g_rmask[t] = m;
    }
}

// ---------------------------------------------------------------------------
// Split-precision conversion kernels (gates GEMM inputs)
// ---------------------------------------------------------------------------
__global__ void conv_x(const float* __restrict__ x)
{
    int i = blockIdx.x * blockDim.x + threadIdx.x;
    if (i < NB * TT * DD) {
        float v = x[i];
        __nv_bfloat16 h = __float2bfloat16(v);
        g_xhi[i] = h;
        g_xlo[i] = __float2bfloat16(v - __bfloat162float(h));
    }
}

__global__ void conv_w(const float* __restrict__ w)
{
    int i = blockIdx.x * blockDim.x + threadIdx.x;
    if (i < DD * GG) {
        int k = i / GG;
        int n = i % GG;
        float v = w[i];
        __nv_bfloat16 h = __float2bfloat16(v);
        g_whi[(size_t)n * DD + k] = h;
        g_wlo[(size_t)n * DD + k] = __float2bfloat16(v - __bfloat162float(h));
    }
}

// ---------------------------------------------------------------------------
// Tensor-core gates GEMM (unchanged from R10 — validated, 435us)
// ---------------------------------------------------------------------------
#define ASTR 40

__global__ __launch_bounds__(256) void mma_gates(const float* __restrict__ bias)
{
    __shared__ __nv_bfloat16 sAh[128][ASTR];
    __shared__ __nv_bfloat16 sAl[128][ASTR];
    __shared__ __nv_bfloat16 sBh[128][ASTR];
    __shared__ __nv_bfloat16 sBl[128][ASTR];

    const int tid = threadIdx.x;
    const int lane = tid & 31;
    const int wid = tid >> 5;
    const int wm = wid & 1;
    const int wn = wid >> 1;
    const int bn = blockIdx.x * 128;
    const int bm = blockIdx.y * 128;

    float c[4][4][4];
#pragma unroll
    for (int i = 0; i < 4; i++)
#pragma unroll
        for (int j = 0; j < 4; j++)
#pragma unroll
            for (int q = 0; q < 4; q++) c[i][j][q] = 0.0f;

    const int a_row = wm * 64 + (lane & 7) + ((lane >> 3) & 1) * 8;
    const int a_col = ((lane >> 4) & 1) * 8;
    const int b_row = wn * 32 + (lane & 7) + ((lane >> 4) & 1) * 8;
    const int b_col = ((lane >> 3) & 1) * 8;

    for (int kc = 0; kc < 16; kc++) {
        for (int i = tid; i < 512; i += 256) {
            int row = i >> 2;
            int c8 = (i & 3) * 8;
            size_t ga = (size_t)(bm + row) * DD + kc * 32 + c8;
            size_t gb = (size_t)(bn + row) * DD + kc * 32 + c8;
            *(uint4*)&sAh[row][c8] = *(const uint4*)&g_xhi[ga];
            *(uint4*)&sAl[row][c8] = *(const uint4*)&g_xlo[ga];
            *(uint4*)&sBh[row][c8] = *(const uint4*)&g_whi[gb];
            *(uint4*)&sBl[row][c8] = *(const uint4*)&g_wlo[gb];
        }
        __syncthreads();

#pragma unroll
        for (int ks = 0; ks < 2; ks++) {
            const int k0 = ks * 16;
            uint32_t ah[4][4], al[4][4], bh[2][4], bl[2][4];
#pragma unroll
            for (int mi = 0; mi < 4; mi++) {
                uint32_t adr = smem_u32(&sAh[a_row + mi * 16][k0 + a_col]);
                LDSM_X4(ah[mi], adr);
                adr = smem_u32(&sAl[a_row + mi * 16][k0 + a_col]);
                LDSM_X4(al[mi], adr);
            }
#pragma unroll
            for (int j = 0; j < 2; j++) {
                uint32_t adr = smem_u32(&sBh[b_row + j * 16][k0 + b_col]);
                LDSM_X4(bh[j], adr);
                adr = smem_u32(&sBl[b_row + j * 16][k0 + b_col]);
                LDSM_X4(bl[j], adr);
            }
#pragma unroll
            for (int mi = 0; mi < 4; mi++) {
#pragma unroll
                for (int nj = 0; nj < 4; nj++) {
                    int j = nj >> 1, p = (nj & 1) * 2;
                    MMA_BF16(c[mi][nj], ah[mi], bh[j][p], bh[j][p + 1]);
                    MMA_BF16(c[mi][nj], ah[mi], bl[j][p], bl[j][p + 1]);
                    MMA_BF16(c[mi][nj], al[mi], bh[j][p], bh[j][p + 1]);
                }
            }
        }
        __syncthreads();
    }

#pragma unroll
    for (int mi = 0; mi < 4; mi++) {
#pragma unroll
        for (int nj = 0; nj < 4; nj++) {
            int r = bm + wm * 64 + mi * 16 + (lane >> 2);
            int cn = bn + wn * 32 + nj * 8 + (lane & 3) * 2;
            float b0 = bias[cn], b1 = bias[cn + 1];
            float2 v0 = make_float2(c[mi][nj][0] + b0, c[mi][nj][1] + b1);
            float2 v1 = make_float2(c[mi][nj][2] + b0, c[mi][nj][3] + b1);
            *(float2*)&g_gates[(size_t)r * GG + cn] = v0;
            *(float2*)&g_gates[(size_t)(r + 8) * GG + cn] = v1;
        }
    }
}

extern __shared__ float dsm[];

// ---------------------------------------------------------------------------
// Persistent recurrence kernel v6: per-step GEMMs on tensor cores.
// CTA x owns zr cols [16x,16x+16) and a cols [8x,8x+8), all 32 batches.
// smem layout (bytes):
//   sWh @ 0      : 24 x 1032 bf16 (49536)   recurrent weights hi
//   sWl @ 49536  : 24 x 1032 bf16 (49536)   lo
//   sHh @ 99072  : 32 x 1032 bf16 (66048)   h (then rh) hi
//   sHl @ 165120 : 32 x 1032 bf16 (66048)   lo            -> total 231168
// ---------------------------------------------------------------------------
#define HSTR 2064    // row stride bytes (1032 bf16) ; 2064 % 128 == 16
#define OFF_WH 0
#define OFF_WL 49536
#define OFF_HH 99072
#define OFF_HL 165120
#define SMEM_GRU2 231168

__global__ __launch_bounds__(NTHR, 1) void gru_persistent(
    const float* __restrict__ w_h, const float* __restrict__ h0,
    float* out0, float* __restrict__ out1)
{
    char* sm = (char*)dsm;
    const int x = blockIdx.x;
    const int tid = threadIdx.x;
    const int lane = tid & 31;
    const int wid = tid >> 5;
    const int leaf = x & 15;

    // ---- one-time weight preload + split into sWh/sWl ----
    for (int i = tid; i < 24 * 1024; i += NTHR) {
        int c = i >> 10, k = i & 1023;
        int gcol = (c < 16) ? (x * 16 + c) : (2048 + x * 8 + (c - 16));
        float v = w_h[(size_t)k * GG + gcol];
        __nv_bfloat16 h = __float2bfloat16(v);
        __nv_bfloat16 l = __float2bfloat16(v - __bfloat162float(h));
        *(__nv_bfloat16*)(sm + OFF_WH + c * HSTR + 2 * k) = h;
        *(__nv_bfloat16*)(sm + OFF_WL + c * HSTR + 2 * k) = l;
    }
    __syncthreads();

    const float4* h0_4 = (const float4*)h0;
    const float4* out0_4 = (const float4*)out0;
    const float4* gzr4 = (const float4*)g_zr;

    // ldmatrix base addresses (validated fragment pattern from mma_gates)
    const int mi = wid & 1;   // m-tile for MMA warps (wid<2)
    uint32_t aAh = smem_u32(sm + OFF_HH
        + (mi * 16 + (lane & 7) + ((lane >> 3) & 1) * 8) * HSTR
        + ((lane >> 4) & 1) * 16);
    uint32_t aAl = aAh + (OFF_HL - OFF_HH);
    uint32_t aBh = smem_u32(sm + OFF_WH
        + ((lane & 7) + ((lane >> 4) & 1) * 8) * HSTR
        + ((lane >> 3) & 1) * 16);
    uint32_t aBl = aBh + (OFF_WL - OFF_WH);
    uint32_t aB2h = aBh + 16 * HSTR;   // phase2 B: sW rows 16-23 (X4 overspill OK)
    uint32_t aB2l = aBl + 16 * HSTR;

    const int frow = lane >> 2;        // fragment row within 8
    const int fcol = (lane & 3) * 2;   // fragment col pair

    for (int t = 0; t < TT; t++) {
        unsigned rm = g_rmask[t];
        int tp = (t > 0) ? (t - 1) : 0;

        // ---- prefetch gates for this step (independent of other CTAs) ----
        float2 gx1[2][2], gx2[2];
        if (wid < 2) {
            int b0 = mi * 16 + frow;
#pragma unroll
            for (int hh = 0; hh < 2; hh++) {
                size_t grow = ((size_t)(b0 + hh * 8) * TT + t) * GG;
#pragma unroll
                for (int nj = 0; nj < 2; nj++)
                    gx1[nj][hh] = *(const float2*)&g_gates[grow + x * 16 + nj * 8 + fcol];
                gx2[hh] = *(const float2*)&g_gates[grow + 2048 + x * 8 + fcol];
            }
        }

        // ---- wait for barrier 2 of previous step (h(t-1) ready) ----
        if (t > 0) {
            unsigned n = 2u * t;
            if (tid == 0) {
                while (*(volatile unsigned*)&g_release < n) __nanosleep(32);
                __threadfence();
            }
            __syncthreads();
        }

        // ---- stage h_eff (fp32 -> bf16 hi/lo) into sHh/sHl ----
        for (int i = tid; i < 8192; i += NTHR) {
            int b = i >> 8, k4 = i & 255;
            float4 v;
            if ((rm >> b) & 1u)
                v = h0_4[k4];
            else
                v = __ldcg(&out0_4[((size_t)b * TT + tp) * 256 + k4]);
            uint2 hi, lo;
            split4(v, hi, lo);
            *(uint2*)(sm + OFF_HH + b * HSTR + k4 * 8) = hi;
            *(uint2*)(sm + OFF_HL + b * HSTR + k4 * 8) = lo;
        }
        __syncthreads();

        // ---- phase1 MMA: zr = sigmoid(gx + h @ Wzr) ----
        if (wid < 2) {
            float acc[6][4];
#pragma unroll
            for (int q = 0; q < 6; q++)
#pragma unroll
                for (int e = 0; e < 4; e++) acc[q][e] = 0.0f;
            uint32_t pAh = aAh, pAl = aAl, pBh = aBh, pBl = aBl;
#pragma unroll 4
            for (int ks = 0; ks < 64; ks++) {
                uint32_t Ah[4], Al[4], Bh[4], Bl[4];
                LDSM_X4(Ah, pAh); LDSM_X4(Al, pAl);
                LDSM_X4(Bh, pBh); LDSM_X4(Bl, pBl);
                MMA_BF16(acc[0], Ah, Bh[0], Bh[1]);
                MMA_BF16(acc[1], Ah, Bh[2], Bh[3]);
                MMA_BF16(acc[2], Ah, Bl[0], Bl[1]);
                MMA_BF16(acc[3], Ah, Bl[2], Bl[3]);
                MMA_BF16(acc[4], Al, Bh[0], Bh[1]);
                MMA_BF16(acc[5], Al, Bh[2], Bh[3]);
                pAh += 32; pAl += 32; pBh += 32; pBl += 32;
            }
            int b0 = mi * 16 + frow;
#pragma unroll
            for (int nj = 0; nj < 2; nj++) {
                float c0 = acc[nj][0] + acc[nj + 2][0] + acc[nj + 4][0];
                float c1 = acc[nj][1] + acc[nj + 2][1] + acc[nj + 4][1];
                float c2 = acc[nj][2] + acc[nj + 2][2] + acc[nj + 4][2];
                float c3 = acc[nj][3] + acc[nj + 2][3] + acc[nj + 4][3];
                int col = x * 16 + nj * 8 + fcol;
                float2 o0, o1;
                o0.x = 1.0f / (1.0f + __expf(-(gx1[nj][0].x + c0)));
                o0.y = 1.0f / (1.0f + __expf(-(gx1[nj][0].y + c1)));
                o1.x = 1.0f / (1.0f + __expf(-(gx1[nj][1].x + c2)));
                o1.y = 1.0f / (1.0f + __expf(-(gx1[nj][1].y + c3)));
                *(float2*)&g_zr[b0 * 2048 + col] = o0;
                *(float2*)&g_zr[(b0 + 8) * 2048 + col] = o1;
            }
        }

        // ---- barrier 1 (zr visible to all CTAs) ----
        unsigned n1 = 2u * t + 1u;
        __syncthreads();
        if (tid == 0) {
            __threadfence();
            unsigned o = atomicAdd(&g_leaf[leaf], 1u);
            if (o == n1 * 8u - 1u) {
                unsigned o2 = atomicAdd(&g_root, 1u);
                if (o2 == n1 * 16u - 1u) atomicExch(&g_release, n1);
            }
            while (*(volatile unsigned*)&g_release < n1) __nanosleep(32);
            __threadfence();
        }
        __syncthreads();

        // ---- restage rh = r * h (read smem h, gmem r; rewrite sH) ----
        for (int i = tid; i < 8192; i += NTHR) {
            int b = i >> 8, k4 = i & 255;
            uint2 hi = *(uint2*)(sm + OFF_HH + b * HSTR + k4 * 8);
            uint2 lo = *(uint2*)(sm + OFF_HL + b * HSTR + k4 * 8);
            float4 r = __ldcg(&gzr4[b * 512 + 256 + k4]);
            float2 h01 = __bfloat1622float2(*(__nv_bfloat162*)&hi.x);
            float2 h23 = __bfloat1622float2(*(__nv_bfloat162*)&hi.y);
            float2 l01 = __bfloat1622float2(*(__nv_bfloat162*)&lo.x);
            float2 l23 = __bfloat1622float2(*(__nv_bfloat162*)&lo.y);
            float4 v;
            v.x = r.x * (h01.x + l01.x);
            v.y = r.y * (h01.y + l01.y);
            v.z = r.z * (h23.x + l23.x);
            v.w = r.w * (h23.y + l23.y);
            uint2 nhi, nlo;
            split4(v, nhi, nlo);
            *(uint2*)(sm + OFF_HH + b * HSTR + k4 * 8) = nhi;
            *(uint2*)(sm + OFF_HL + b * HSTR + k4 * 8) = nlo;
        }
        __syncthreads();

        // ---- phase2 MMA: a = tanh(gx + rh @ Wa); finalize ----
        if (wid < 2) {
            float acc[3][4];
#pragma unroll
            for (int q = 0; q < 3; q++)
#pragma unroll
                for (int e = 0; e < 4; e++) acc[q][e] = 0.0f;
            uint32_t pAh = aAh, pAl = aAl, pBh = aB2h, pBl = aB2l;
#pragma unroll 4
            for (int ks = 0; ks < 64; ks++) {
                uint32_t Ah[4], Al[4], Bh[4], Bl[4];
                LDSM_X4(Ah, pAh); LDSM_X4(Al, pAl);
                LDSM_X4(Bh, pBh); LDSM_X4(Bl, pBl);
                MMA_BF16(acc[0], Ah, Bh[0], Bh[1]);
                MMA_BF16(acc[1], Ah, Bl[0], Bl[1]);
                MMA_BF16(acc[2], Al, Bh[0], Bh[1]);
                pAh += 32; pAl += 32; pBh += 32; pBl += 32;
            }
            float cc[4];
#pragma unroll
            for (int e = 0; e < 4; e++)
                cc[e] = acc[0][e] + acc[1][e] + acc[2][e];

            int col = x * 8 + fcol;
#pragma unroll
            for (int hh = 0; hh < 2; hh++) {
                int b = mi * 16 + frow + hh * 8;
                float a0 = tanhf(gx2[hh].x + cc[hh * 2 + 0]);
                float a1 = tanhf(gx2[hh].y + cc[hh * 2 + 1]);
                float2 z = *(const float2*)&g_zr[b * 2048 + col];
                float2 hw;
                if ((rm >> b) & 1u)
                    hw = *(const float2*)&h0[col];
                else
                    hw = *(const float2*)&out0[((size_t)b * TT + tp) * HH + col];
                float2 hn;
                hn.x = (1.0f - z.x) * hw.x + z.x * a0;
                hn.y = (1.0f - z.y) * hw.y + z.y * a1;
                size_t o = ((size_t)b * TT + t) * HH + col;
                *(float2*)&out0[o] = hn;
                *(float2*)&out1[o] = hn;
            }
        }

        // ---- barrier 2 arrive (h(t) ready); wait at next loop top ----
        unsigned n2 = 2u * t + 2u;
        __syncthreads();
        if (tid == 0) {
            __threadfence();
            unsigned o = atomicAdd(&g_leaf[leaf], 1u);
            if (o == n2 * 8u - 1u) {
                unsigned o2 = atomicAdd(&g_root, 1u);
                if (o2 == n2 * 16u - 1u) atomicExch(&g_release, n2);
            }
        }
    }
}

// ---------------------------------------------------------------------------
// Epilogue: runs BEFORE gru each replay — zero barrier state + write outh.
// ---------------------------------------------------------------------------
__global__ void epilogue(const float* __restrict__ h0, float* __restrict__ dst)
{
    int i = blockIdx.x * blockDim.x + threadIdx.x;
    if (i < HH) dst[i] = h0[i];
    if (i < 16) g_leaf[i] = 0;
    if (i == 16) g_root = 0;
    if (i == 17) g_release = 0;
}

// ---------------------------------------------------------------------------
extern "C" void kernel_launch(void* const* d_in, const int* in_sizes, int n_in,
                              void* d_out, int out_size)
{
    const float* x = (const float*)d_in[0];
    const unsigned char* reset_raw = (const unsigned char*)d_in[1];
    const float* w_i = (const float*)d_in[2];
    const float* w_h = (const float*)d_in[3];
    const float* b = (const float*)d_in[4];
    const float* h0 = (const float*)d_in[5];

    float* out0 = (float*)d_out;
    float* out1 = out0 + (size_t)NB * TT * HH;
    float* outh = out1 + (size_t)NB * TT * HH;

    cudaFuncSetAttribute(gru_persistent,
                         cudaFuncAttributeMaxDynamicSharedMemorySize, SMEM_GRU2);

    // 0) reset masks + split-precision conversion
    prep_reset<<<1, 512>>>(reset_raw);
    conv_x<<<(NB * TT * DD + 255) / 256, 256>>>(x);
    conv_w<<<(DD * GG + 255) / 256, 256>>>(w_i);

    // 1) gates = x @ w_i + b via mma.sync bf16 (split precision, f32 accum)
    {
        dim3 grid(GG / 128, (NB * TT) / 128);
        mma_gates<<<grid, 256>>>(b);
    }

    // 2) barrier state reset + third output
    epilogue<<<1, 1024>>>(h0, outh);

    // 3) full recurrence in ONE persistent kernel (tensor-core per-step GEMMs)
    gru_persistent<<<NCTA, NTHR, SMEM_GRU2>>>(w_h, h0, out0, out1);
}

// round 12
// speedup vs baseline: 1.7654x; 1.0653x over previous
#include <cuda_runtime.h>
#include <cuda_bf16.h>
#include <cstdint>

// Problem constants
#define NB 32      // batch
#define TT 512     // time steps
#define DD 512     // input dim
#define HH 1024    // hidden dim
#define GG 3072    // 3*H

#define NCTA 128   // persistent grid
#define NTHR 512

// Scratch (module-load allocated; no runtime alloc)
__device__ float g_gates[(size_t)NB * TT * GG];  // 16384 x 3072
__device__ float g_zr[NB * 2 * HH];              // z region used (cols 0..1023)
__device__ unsigned g_rmask[TT];                 // per-step reset bitmasks

// bf16 hi/lo exchange buffers (uint32 = packed bf16 col-pair)
__device__ uint32_t g_hh[NB * 512];   // h(t) hi
__device__ uint32_t g_hl[NB * 512];   // h(t) lo
__device__ uint32_t g_rhh[NB * 512];  // rh hi
__device__ uint32_t g_rhl[NB * 512];  // rh lo
__device__ uint32_t g_h0h[512];       // h0 hi
__device__ uint32_t g_h0l[512];       // h0 lo

// split-precision bf16 operands for the gates GEMM
__device__ __nv_bfloat16 g_xhi[(size_t)NB * TT * DD];
__device__ __nv_bfloat16 g_xlo[(size_t)NB * TT * DD];
__device__ __nv_bfloat16 g_whi[(size_t)GG * DD];   // transposed [n][k]
__device__ __nv_bfloat16 g_wlo[(size_t)GG * DD];

// Hierarchical barrier state (zeroed by epilogue BEFORE gru each replay)
__device__ unsigned g_leaf[16];
__device__ unsigned g_root;
__device__ unsigned g_release;

__device__ __forceinline__ uint32_t smem_u32(const void* p)
{
    uint32_t a;
    asm("{ .reg .u64 t; cvta.to.shared.u64 t, %1; cvt.u32.u64 %0, t; }"
        : "=r"(a) : "l"(p));
    return a;
}

// ldmatrix x4 (four 8x8 b16 tiles)
#define LDSM_X4(r, a) \
    asm volatile("ldmatrix.sync.aligned.m8n8.x4.shared.b16 {%0,%1,%2,%3}, [%4];" \
        : "=r"((r)[0]), "=r"((r)[1]), "=r"((r)[2]), "=r"((r)[3]) : "r"(a))

// bf16 m16n8k16 mma, f32 accum
#define MMA_BF16(c, a, b0, b1) \
    asm volatile("mma.sync.aligned.m16n8k16.row.col.f32.bf16.bf16.f32 " \
        "{%0,%1,%2,%3}, {%4,%5,%6,%7}, {%8,%9}, {%0,%1,%2,%3};" \
        : "+f"((c)[0]), "+f"((c)[1]), "+f"((c)[2]), "+f"((c)[3]) \
        : "r"((a)[0]), "r"((a)[1]), "r"((a)[2]), "r"((a)[3]), "r"(b0), "r"(b1))

// split float2 -> packed bf16 hi/lo uint32s
__device__ __forceinline__ void split2(float2 v, uint32_t& hi, uint32_t& lo)
{
    __nv_bfloat162 h2 = __floats2bfloat162_rn(v.x, v.y);
    float2 hf = __bfloat1622float2(h2);
    __nv_bfloat162 l2 = __floats2bfloat162_rn(v.x - hf.x, v.y - hf.y);
    hi = *(uint32_t*)&h2;
    lo = *(uint32_t*)&l2;
}

__device__ __forceinline__ float2 join2(uint32_t hi, uint32_t lo)
{
    float2 h = __bfloat1622float2(*(__nv_bfloat162*)&hi);
    float2 l = __bfloat1622float2(*(__nv_bfloat162*)&lo);
    return make_float2(h.x + l.x, h.y + l.y);
}

// ---------------------------------------------------------------------------
// Prep: detect reset dtype (bool8 vs int32), build per-step bitmasks.
// ---------------------------------------------------------------------------
__global__ void prep_reset(const unsigned char* __restrict__ raw)
{
    __shared__ int s_bool8;
    int tid = threadIdx.x;
    if (tid == 0) s_bool8 = 0;
    __syncthreads();
    for (int i = tid; i < 4096; i += blockDim.x)
        if ((i & 3) != 0 && raw[i] != 0) s_bool8 = 1;
    __syncthreads();
    bool b8 = (s_bool8 != 0);
    const int* r32 = (const int*)raw;
    for (int t = tid; t < TT; t += blockDim.x) {
        unsigned m = 0;
        for (int b = 0; b < NB; b++) {
            bool rv = b8 ? (raw[b * TT + t] != 0) : (r32[b * TT + t] != 0);
            if (rv) m |= (1u << b);
        }
        if (t == 0) m = 0xFFFFFFFFu;
        g_rmask[t] = m;
    }
}

// ---------------------------------------------------------------------------
// Split-precision conversion kernels (gates GEMM inputs)
// ---------------------------------------------------------------------------
__global__ void conv_x(const float* __restrict__ x)
{
    int i = blockIdx.x * blockDim.x + threadIdx.x;
    if (i < NB * TT * DD) {
        float v = x[i];
        __nv_bfloat16 h = __float2bfloat16(v);
        g_xhi[i] = h;
        g_xlo[i] = __float2bfloat16(v - __bfloat162float(h));
    }
}

__global__ void conv_w(const float* __restrict__ w)
{
    int i = blockIdx.x * blockDim.x + threadIdx.x;
    if (i < DD * GG) {
        int k = i / GG;
        int n = i % GG;
        float v = w[i];
        __nv_bfloat16 h = __float2bfloat16(v);
        g_whi[(size_t)n * DD + k] = h;
        g_wlo[(size_t)n * DD + k] = __float2bfloat16(v - __bfloat162float(h));
    }
}

// ---------------------------------------------------------------------------
// Tensor-core gates GEMM (unchanged from R10 — validated, 435us)
// ---------------------------------------------------------------------------
#define ASTR 40

__global__ __launch_bounds__(256) void mma_gates(const float* __restrict__ bias)
{
    __shared__ __nv_bfloat16 sAh[128][ASTR];
    __shared__ __nv_bfloat16 sAl[128][ASTR];
    __shared__ __nv_bfloat16 sBh[128][ASTR];
    __shared__ __nv_bfloat16 sBl[128][ASTR];

    const int tid = threadIdx.x;
    const int lane = tid & 31;
    const int wid = tid >> 5;
    const int wm = wid & 1;
    const int wn = wid >> 1;
    const int bn = blockIdx.x * 128;
    const int bm = blockIdx.y * 128;

    float c[4][4][4];
#pragma unroll
    for (int i = 0; i < 4; i++)
#pragma unroll
        for (int j = 0; j < 4; j++)
#pragma unroll
            for (int q = 0; q < 4; q++) c[i][j][q] = 0.0f;

    const int a_row = wm * 64 + (lane & 7) + ((lane >> 3) & 1) * 8;
    const int a_col = ((lane >> 4) & 1) * 8;
    const int b_row = wn * 32 + (lane & 7) + ((lane >> 4) & 1) * 8;
    const int b_col = ((lane >> 3) & 1) * 8;

    for (int kc = 0; kc < 16; kc++) {
        for (int i = tid; i < 512; i += 256) {
            int row = i >> 2;
            int c8 = (i & 3) * 8;
            size_t ga = (size_t)(bm + row) * DD + kc * 32 + c8;
            size_t gb = (size_t)(bn + row) * DD + kc * 32 + c8;
            *(uint4*)&sAh[row][c8] = *(const uint4*)&g_xhi[ga];
            *(uint4*)&sAl[row][c8] = *(const uint4*)&g_xlo[ga];
            *(uint4*)&sBh[row][c8] = *(const uint4*)&g_whi[gb];
            *(uint4*)&sBl[row][c8] = *(const uint4*)&g_wlo[gb];
        }
        __syncthreads();

#pragma unroll
        for (int ks = 0; ks < 2; ks++) {
            const int k0 = ks * 16;
            uint32_t ah[4][4], al[4][4], bh[2][4], bl[2][4];
#pragma unroll
            for (int mi = 0; mi < 4; mi++) {
                uint32_t adr = smem_u32(&sAh[a_row + mi * 16][k0 + a_col]);
                LDSM_X4(ah[mi], adr);
                adr = smem_u32(&sAl[a_row + mi * 16][k0 + a_col]);
                LDSM_X4(al[mi], adr);
            }
#pragma unroll
            for (int j = 0; j < 2; j++) {
                uint32_t adr = smem_u32(&sBh[b_row + j * 16][k0 + b_col]);
                LDSM_X4(bh[j], adr);
                adr = smem_u32(&sBl[b_row + j * 16][k0 + b_col]);
                LDSM_X4(bl[j], adr);
            }
#pragma unroll
            for (int mi = 0; mi < 4; mi++) {
#pragma unroll
                for (int nj = 0; nj < 4; nj++) {
                    int j = nj >> 1, p = (nj & 1) * 2;
                    MMA_BF16(c[mi][nj], ah[mi], bh[j][p], bh[j][p + 1]);
                    MMA_BF16(c[mi][nj], ah[mi], bl[j][p], bl[j][p + 1]);
                    MMA_BF16(c[mi][nj], al[mi], bh[j][p], bh[j][p + 1]);
                }
            }
        }
        __syncthreads();
    }

#pragma unroll
    for (int mi = 0; mi < 4; mi++) {
#pragma unroll
        for (int nj = 0; nj < 4; nj++) {
            int r = bm + wm * 64 + mi * 16 + (lane >> 2);
            int cn = bn + wn * 32 + nj * 8 + (lane & 3) * 2;
            float b0 = bias[cn], b1 = bias[cn + 1];
            float2 v0 = make_float2(c[mi][nj][0] + b0, c[mi][nj][1] + b1);
            float2 v1 = make_float2(c[mi][nj][2] + b0, c[mi][nj][3] + b1);
            *(float2*)&g_gates[(size_t)r * GG + cn] = v0;
            *(float2*)&g_gates[(size_t)(r + 8) * GG + cn] = v1;
        }
    }
}

extern __shared__ float dsm[];

// ---------------------------------------------------------------------------
// Persistent recurrence kernel v7: bf16 hi/lo exchange, producer-computed rh.
// CTA x<64 owns z cols [16x,16x+16); CTA x>=64 owns r cols [16(x-64),...).
// All CTAs own a cols [8x, 8x+8).
// smem layout identical to v6: sWh/sWl (24x1032 bf16) + sHh/sHl (32x1032 bf16)
// ---------------------------------------------------------------------------
#define HSTR 2064
#define OFF_WH 0
#define OFF_WL 49536
#define OFF_HH 99072
#define OFF_HL 165120
#define SMEM_GRU2 231168

__global__ __launch_bounds__(NTHR, 1) void gru_persistent(
    const float* __restrict__ w_h, const float* __restrict__ h0,
    float* out0, float* __restrict__ out1)
{
    char* sm = (char*)dsm;
    const int x = blockIdx.x;
    const int tid = threadIdx.x;
    const int lane = tid & 31;
    const int wid = tid >> 5;
    const int leaf = x & 15;

    // ---- one-time weight preload + split into sWh/sWl ----
    for (int i = tid; i < 24 * 1024; i += NTHR) {
        int c = i >> 10, k = i & 1023;
        int gcol = (c < 16) ? (x * 16 + c) : (2048 + x * 8 + (c - 16));
        float v = w_h[(size_t)k * GG + gcol];
        __nv_bfloat16 h = __float2bfloat16(v);
        __nv_bfloat16 l = __float2bfloat16(v - __bfloat162float(h));
        *(__nv_bfloat16*)(sm + OFF_WH + c * HSTR + 2 * k) = h;
        *(__nv_bfloat16*)(sm + OFF_WL + c * HSTR + 2 * k) = l;
    }
    __syncthreads();

    // ldmatrix base addresses (validated fragment pattern)
    const int mi = wid & 1;
    uint32_t aAh = smem_u32(sm + OFF_HH
        + (mi * 16 + (lane & 7) + ((lane >> 3) & 1) * 8) * HSTR
        + ((lane >> 4) & 1) * 16);
    uint32_t aAl = aAh + (OFF_HL - OFF_HH);
    uint32_t aBh = smem_u32(sm + OFF_WH
        + ((lane & 7) + ((lane >> 4) & 1) * 8) * HSTR
        + ((lane >> 3) & 1) * 16);
    uint32_t aBl = aBh + (OFF_WL - OFF_WH);
    uint32_t aB2h = aBh + 16 * HSTR;
    uint32_t aB2l = aBl + 16 * HSTR;

    const int frow = lane >> 2;
    const int fcol = (lane & 3) * 2;

    const uint2* hh2 = (const uint2*)g_hh;
    const uint2* hl2 = (const uint2*)g_hl;
    const uint2* rhh2 = (const uint2*)g_rhh;
    const uint2* rhl2 = (const uint2*)g_rhl;
    const uint2* h0h2 = (const uint2*)g_h0h;
    const uint2* h0l2 = (const uint2*)g_h0l;

    for (int t = 0; t < TT; t++) {
        unsigned rm = g_rmask[t];

        // ---- prefetch gates for this step ----
        float2 gx1[2][2], gx2[2];
        if (wid < 2) {
            int b0 = mi * 16 + frow;
#pragma unroll
            for (int hh = 0; hh < 2; hh++) {
                size_t grow = ((size_t)(b0 + hh * 8) * TT + t) * GG;
#pragma unroll
                for (int nj = 0; nj < 2; nj++)
                    gx1[nj][hh] = *(const float2*)&g_gates[grow + x * 16 + nj * 8 + fcol];
                gx2[hh] = *(const float2*)&g_gates[grow + 2048 + x * 8 + fcol];
            }
        }

        // ---- wait for barrier 2 of previous step (h(t-1) bf16 ready) ----
        if (t > 0) {
            unsigned n = 2u * t;
            if (tid == 0) {
                while (*(volatile unsigned*)&g_release < n) __nanosleep(32);
                __threadfence();
            }
            __syncthreads();
        }

        // ---- stage h_eff bf16 (pure copy, no conversion) ----
        for (int i = tid; i < 8192; i += NTHR) {
            int b = i >> 8, k4 = i & 255;
            uint2 hi, lo;
            if ((rm >> b) & 1u) {
                hi = __ldg(&h0h2[k4]);
                lo = __ldg(&h0l2[k4]);
            } else {
                hi = __ldcg(&hh2[b * 256 + k4]);
                lo = __ldcg(&hl2[b * 256 + k4]);
            }
            *(uint2*)(sm + OFF_HH + b * HSTR + k4 * 8) = hi;
            *(uint2*)(sm + OFF_HL + b * HSTR + k4 * 8) = lo;
        }
        __syncthreads();

        // ---- phase1 MMA: zr pre-activations ----
        if (wid < 2) {
            float acc[6][4];
#pragma unroll
            for (int q = 0; q < 6; q++)
#pragma unroll
                for (int e = 0; e < 4; e++) acc[q][e] = 0.0f;
            uint32_t pAh = aAh, pAl = aAl, pBh = aBh, pBl = aBl;
#pragma unroll 4
            for (int ks = 0; ks < 64; ks++) {
                uint32_t Ah[4], Al[4], Bh[4], Bl[4];
                LDSM_X4(Ah, pAh); LDSM_X4(Al, pAl);
                LDSM_X4(Bh, pBh); LDSM_X4(Bl, pBl);
                MMA_BF16(acc[0], Ah, Bh[0], Bh[1]);
                MMA_BF16(acc[1], Ah, Bh[2], Bh[3]);
                MMA_BF16(acc[2], Ah, Bl[0], Bl[1]);
                MMA_BF16(acc[3], Ah, Bl[2], Bl[3]);
                MMA_BF16(acc[4], Al, Bh[0], Bh[1]);
                MMA_BF16(acc[5], Al, Bh[2], Bh[3]);
                pAh += 32; pAl += 32; pBh += 32; pBl += 32;
            }
            int b0 = mi * 16 + frow;
#pragma unroll
            for (int nj = 0; nj < 2; nj++) {
                float c0 = acc[nj][0] + acc[nj + 2][0] + acc[nj + 4][0];
                float c1 = acc[nj][1] + acc[nj + 2][1] + acc[nj + 4][1];
                float c2 = acc[nj][2] + acc[nj + 2][2] + acc[nj + 4][2];
                float c3 = acc[nj][3] + acc[nj + 2][3] + acc[nj + 4][3];
                float2 s0, s1;
                s0.x = 1.0f / (1.0f + __expf(-(gx1[nj][0].x + c0)));
                s0.y = 1.0f / (1.0f + __expf(-(gx1[nj][0].y + c1)));
                s1.x = 1.0f / (1.0f + __expf(-(gx1[nj][1].x + c2)));
                s1.y = 1.0f / (1.0f + __expf(-(gx1[nj][1].y + c3)));
                if (x < 64) {
                    // z-owner: write z fp32 for finalize
                    int col = x * 16 + nj * 8 + fcol;
                    *(float2*)&g_zr[b0 * 2048 + col] = s0;
                    *(float2*)&g_zr[(b0 + 8) * 2048 + col] = s1;
                } else {
                    // r-owner: compute rh = r * h, split bf16, write
                    int col = (x - 64) * 16 + nj * 8 + fcol;   // 0..1023
#pragma unroll
                    for (int hh = 0; hh < 2; hh++) {
                        int b = b0 + hh * 8;
                        float2 rr = hh ? s1 : s0;
                        uint32_t hhi = *(uint32_t*)(sm + OFF_HH + b * HSTR + col * 2);
                        uint32_t hlo = *(uint32_t*)(sm + OFF_HL + b * HSTR + col * 2);
                        float2 hf = join2(hhi, hlo);
                        float2 rh = make_float2(rr.x * hf.x, rr.y * hf.y);
                        uint32_t ohi, olo;
                        split2(rh, ohi, olo);
                        g_rhh[b * 512 + col / 2] = ohi;
                        g_rhl[b * 512 + col / 2] = olo;
                    }
                }
            }
        }

        // ---- barrier 1 (zr / rh visible to all CTAs) ----
        unsigned n1 = 2u * t + 1u;
        __syncthreads();
        if (tid == 0) {
            __threadfence();
            unsigned o = atomicAdd(&g_leaf[leaf], 1u);
            if (o == n1 * 8u - 1u) {
                unsigned o2 = atomicAdd(&g_root, 1u);
                if (o2 == n1 * 16u - 1u) atomicExch(&g_release, n1);
            }
            while (*(volatile unsigned*)&g_release < n1) __nanosleep(32);
            __threadfence();
        }
        __syncthreads();

        // ---- stash h(t-1) + z at own a-cols (before smem is overwritten) ----
        float2 hw[2], zz[2];
        if (wid < 2) {
            int col = x * 8 + fcol;
#pragma unroll
            for (int hh = 0; hh < 2; hh++) {
                int b = mi * 16 + frow + hh * 8;
                uint32_t hhi = *(uint32_t*)(sm + OFF_HH + b * HSTR + col * 2);
                uint32_t hlo = *(uint32_t*)(sm + OFF_HL + b * HSTR + col * 2);
                hw[hh] = join2(hhi, hlo);
                zz[hh] = __ldcg((const float2*)&g_zr[b * 2048 + col]);
            }
        }
        __syncthreads();

        // ---- restage rh bf16 (pure copy) ----
        for (int i = tid; i < 8192; i += NTHR) {
            int b = i >> 8, k4 = i & 255;
            uint2 hi = __ldcg(&rhh2[b * 256 + k4]);
            uint2 lo = __ldcg(&rhl2[b * 256 + k4]);
            *(uint2*)(sm + OFF_HH + b * HSTR + k4 * 8) = hi;
            *(uint2*)(sm + OFF_HL + b * HSTR + k4 * 8) = lo;
        }
        __syncthreads();

        // ---- phase2 MMA: a = tanh(gx + rh @ Wa); finalize ----
        if (wid < 2) {
            float acc[3][4];
#pragma unroll
            for (int q = 0; q < 3; q++)
#pragma unroll
                for (int e = 0; e < 4; e++) acc[q][e] = 0.0f;
            uint32_t pAh = aAh, pAl = aAl, pBh = aB2h, pBl = aB2l;
#pragma unroll 4
            for (int ks = 0; ks < 64; ks++) {
                uint32_t Ah[4], Al[4], Bh[4], Bl[4];
                LDSM_X4(Ah, pAh); LDSM_X4(Al, pAl);
                LDSM_X4(Bh, pBh); LDSM_X4(Bl, pBl);
                MMA_BF16(acc[0], Ah, Bh[0], Bh[1]);
                MMA_BF16(acc[1], Ah, Bl[0], Bl[1]);
                MMA_BF16(acc[2], Al, Bh[0], Bh[1]);
                pAh += 32; pAl += 32; pBh += 32; pBl += 32;
            }
            float cc[4];
#pragma unroll
            for (int e = 0; e < 4; e++)
                cc[e] = acc[0][e] + acc[1][e] + acc[2][e];

            int col = x * 8 + fcol;
#pragma unroll
            for (int hh = 0; hh < 2; hh++) {
                int b = mi * 16 + frow + hh * 8;
                float a0 = tanhf(gx2[hh].x + cc[hh * 2 + 0]);
                float a1 = tanhf(gx2[hh].y + cc[hh * 2 + 1]);
                float2 hn;
                hn.x = (1.0f - zz[hh].x) * hw[hh].x + zz[hh].x * a0;
                hn.y = (1.0f - zz[hh].y) * hw[hh].y + zz[hh].y * a1;
                size_t o = ((size_t)b * TT + t) * HH + col;
                *(float2*)&out0[o] = hn;
                *(float2*)&out1[o] = hn;
                uint32_t nhi, nlo;
                split2(hn, nhi, nlo);
                g_hh[b * 512 + col / 2] = nhi;
                g_hl[b * 512 + col / 2] = nlo;
            }
        }

        // ---- barrier 2 arrive (h(t) bf16 ready); wait at next loop top ----
        unsigned n2 = 2u * t + 2u;
        __syncthreads();
        if (tid == 0) {
            __threadfence();
            unsigned o = atomicAdd(&g_leaf[leaf], 1u);
            if (o == n2 * 8u - 1u) {
                unsigned o2 = atomicAdd(&g_root, 1u);
                if (o2 == n2 * 16u - 1u) atomicExch(&g_release, n2);
            }
        }
    }
}

// ---------------------------------------------------------------------------
// Epilogue: runs BEFORE gru each replay — zero barriers, write outh, split h0.
// ---------------------------------------------------------------------------
__global__ void epilogue(const float* __restrict__ h0, float* __restrict__ dst)
{
    int i = blockIdx.x * blockDim.x + threadIdx.x;
    if (i < HH) dst[i] = h0[i];
    if (i < 512) {
        float2 v = *(const float2*)&h0[i * 2];
        uint32_t hi, lo;
        split2(v, hi, lo);
        g_h0h[i] = hi;
        g_h0l[i] = lo;
    }
    if (i < 16) g_leaf[i] = 0;
    if (i == 16) g_root = 0;
    if (i == 17) g_release = 0;
}

// ---------------------------------------------------------------------------
extern "C" void kernel_launch(void* const* d_in, const int* in_sizes, int n_in,
                              void* d_out, int out_size)
{
    const float* x = (const float*)d_in[0];
    const unsigned char* reset_raw = (const unsigned char*)d_in[1];
    const float* w_i = (const float*)d_in[2];
    const float* w_h = (const float*)d_in[3];
    const float* b = (const float*)d_in[4];
    const float* h0 = (const float*)d_in[5];

    float* out0 = (float*)d_out;
    float* out1 = out0 + (size_t)NB * TT * HH;
    float* outh = out1 + (size_t)NB * TT * HH;

    cudaFuncSetAttribute(gru_persistent,
                         cudaFuncAttributeMaxDynamicSharedMemorySize, SMEM_GRU2);

    // 0) reset masks + split-precision conversion
    prep_reset<<<1, 512>>>(reset_raw);
    conv_x<<<(NB * TT * DD + 255) / 256, 256>>>(x);
    conv_w<<<(DD * GG + 255) / 256, 256>>>(w_i);

    // 1) gates = x @ w_i + b via mma.sync bf16 (split precision, f32 accum)
    {
        dim3 grid(GG / 128, (NB * TT) / 128);
        mma_gates<<<grid, 256>>>(b);
    }

    // 2) barrier state reset + third output + h0 bf16 split
    epilogue<<<1, 1024>>>(h0, outh);

    // 3) full recurrence in ONE persistent kernel
    gru_persistent<<<NCTA, NTHR, SMEM_GRU2>>>(w_h, h0, out0, out1);
}